// round 3
// baseline (speedup 1.0000x reference)
#include <cuda_runtime.h>
#include <cuda_bf16.h>
#include <math.h>

// ---------------------------------------------------------------------------
// Problem constants
// ---------------------------------------------------------------------------
#define NB 8
#define NPTS 2048
#define BNTOT (NB*NPTS)          // 16384
#define KNN 20
#define MEDGE (BNTOT*KNN)        // 327680
#define NEG_SLOPE 0.2f
#define BN_EPS 1e-5f

// ---------------------------------------------------------------------------
// Scratch (device globals -- no allocation allowed)
// ---------------------------------------------------------------------------
__device__ float g_f0  [BNTOT*3];
__device__ float g_x1  [BNTOT*64];
__device__ float g_x2  [BNTOT*64];
__device__ float g_x3  [BNTOT*128];
__device__ float g_x4  [BNTOT*256];
__device__ float g_pd  [(size_t)NB*NPTS*NPTS];       // 134 MB
__device__ int   g_idx [MEDGE];
__device__ float g_wa  [256*128];
__device__ float g_wd  [256*128];
__device__ float g_T   [BNTOT*256];
__device__ float g_hmax[BNTOT*256];
__device__ float g_hmin[BNTOT*256];
__device__ float g_P   [BNTOT*256];
__device__ float g_cat [BNTOT*768];
__device__ float g_gmax[NB*256];
__device__ double g_sum [256];
__device__ double g_sum2[256];
__device__ float g_scale[256];
__device__ float g_shift[256];

// ---------------------------------------------------------------------------
// Small elementwise kernels
// ---------------------------------------------------------------------------
__global__ void transpose_in_kernel(const float* __restrict__ x, float* __restrict__ f) {
    int i = blockIdx.x*256 + threadIdx.x;                 // B*3*N = 49152
    if (i >= NB*3*NPTS) return;
    int b = i / (3*NPTS);
    int rem = i - b*3*NPTS;
    int c = rem / NPTS;
    int n = rem - c*NPTS;
    f[(b*NPTS + n)*3 + c] = x[i];
}

__global__ void prep_w_kernel(const float* __restrict__ W, int O, int C,
                              float* __restrict__ wa, float* __restrict__ wd) {
    int i = blockIdx.x*256 + threadIdx.x;
    if (i >= O*C) return;
    int o = i / C, c = i - o*C;
    float a = W[o*2*C + c];
    wa[i] = a;
    wd[i] = W[o*2*C + C + c] - a;
}

__global__ void zero_stats_kernel(double* s, double* s2) {
    int t = threadIdx.x;
    if (t < 256) { s[t] = 0.0; s2[t] = 0.0; }
}

// ---------------------------------------------------------------------------
// Direct squared-distance kernel: pd[b,i,j] = -sum_c (x_i[c]-x_j[c])^2
// ---------------------------------------------------------------------------
__global__ __launch_bounds__(256)
void dist_kernel(const float* __restrict__ feat, float* __restrict__ pd, int C) {
    __shared__ float As[16][129];
    __shared__ float Bs[16][65];
    int b  = blockIdx.z;
    const float* F = feat + (size_t)b*NPTS*C;
    int tid = threadIdx.x;
    int tx = tid & 15;         // col group
    int ty = tid >> 4;         // row group
    int m0 = blockIdx.x * 128;
    int n0 = blockIdx.y * 64;

    float acc[8][4];
#pragma unroll
    for (int i = 0; i < 8; i++)
#pragma unroll
        for (int j = 0; j < 4; j++) acc[i][j] = 0.f;

    for (int k0 = 0; k0 < C; k0 += 16) {
#pragma unroll
        for (int i = 0; i < 8; i++) {
            int e = tid + i*256;
            int c = e & 15, r = e >> 4;
            float v = 0.f;
            if (k0 + c < C) v = F[(size_t)(m0 + r)*C + k0 + c];
            As[c][r] = v;
        }
#pragma unroll
        for (int i = 0; i < 4; i++) {
            int e = tid + i*256;
            int c = e & 15, r = e >> 4;
            float v = 0.f;
            if (k0 + c < C) v = F[(size_t)(n0 + r)*C + k0 + c];
            Bs[c][r] = v;
        }
        __syncthreads();
#pragma unroll
        for (int k = 0; k < 16; k++) {
            float af[8], bf[4];
#pragma unroll
            for (int i = 0; i < 8; i++) af[i] = As[k][ty*8 + i];
#pragma unroll
            for (int j = 0; j < 4; j++) bf[j] = Bs[k][tx*4 + j];
#pragma unroll
            for (int i = 0; i < 8; i++)
#pragma unroll
                for (int j = 0; j < 4; j++) {
                    float d = af[i] - bf[j];
                    acc[i][j] = fmaf(d, d, acc[i][j]);
                }
        }
        __syncthreads();
    }

    float* pdb = pd + (size_t)b*NPTS*NPTS;
#pragma unroll
    for (int i = 0; i < 8; i++) {
        int m = m0 + ty*8 + i;
#pragma unroll
        for (int j = 0; j < 4; j++) {
            int n = n0 + tx*4 + j;
            pdb[(size_t)m*NPTS + n] = -acc[i][j];
        }
    }
}

// ---------------------------------------------------------------------------
// Top-K (K=20) per row, iterative argmax (ties -> lower index)
// ---------------------------------------------------------------------------
__global__ __launch_bounds__(128)
void topk_kernel(const float* __restrict__ pd, int* __restrict__ idx) {
    int bn = blockIdx.x;
    const float* row = pd + (size_t)bn * NPTS;
    __shared__ float v[NPTS];
    __shared__ float rv[128];
    __shared__ int   ri[128];
    int t = threadIdx.x;
    for (int j = t; j < NPTS; j += 128) v[j] = row[j];
    __syncthreads();
    for (int it = 0; it < KNN; it++) {
        float bv = -INFINITY; int bi = 0x7fffffff;
        for (int j = t; j < NPTS; j += 128) {
            float x = v[j];
            if (x > bv || (x == bv && j < bi)) { bv = x; bi = j; }
        }
        rv[t] = bv; ri[t] = bi;
        __syncthreads();
        for (int s = 64; s > 0; s >>= 1) {
            if (t < s) {
                float ov = rv[t+s]; int oi = ri[t+s];
                if (ov > rv[t] || (ov == rv[t] && oi < ri[t])) { rv[t] = ov; ri[t] = oi; }
            }
            __syncthreads();
        }
        if (t == 0) { idx[bn*KNN + it] = ri[0]; v[ri[0]] = -INFINITY; }
        __syncthreads();
    }
}

// ---------------------------------------------------------------------------
// Generic NT GEMM (used for T and the point convs):
// C[m,n] = sum_k A[m,k]*B[n,k]
// ---------------------------------------------------------------------------
__global__ __launch_bounds__(256)
void gemm_nt_kernel(const float* __restrict__ A, const float* __restrict__ B,
                    float* __restrict__ C, int M, int N, int K) {
    __shared__ float As[16][129];
    __shared__ float Bs[16][65];
    int tid = threadIdx.x;
    int tx = tid & 15;
    int ty = tid >> 4;
    int m0 = blockIdx.x * 128;
    int n0 = blockIdx.y * 64;

    float acc[8][4];
#pragma unroll
    for (int i = 0; i < 8; i++)
#pragma unroll
        for (int j = 0; j < 4; j++) acc[i][j] = 0.f;

    for (int k0 = 0; k0 < K; k0 += 16) {
#pragma unroll
        for (int i = 0; i < 8; i++) {
            int e = tid + i*256;
            int c = e & 15, r = e >> 4;
            int m = m0 + r;
            float v = 0.f;
            if (m < M && k0 + c < K) v = A[(size_t)m*K + k0 + c];
            As[c][r] = v;
        }
#pragma unroll
        for (int i = 0; i < 4; i++) {
            int e = tid + i*256;
            int c = e & 15, r = e >> 4;
            float v = 0.f;
            if (k0 + c < K) v = B[(size_t)(n0 + r)*K + k0 + c];
            Bs[c][r] = v;
        }
        __syncthreads();
#pragma unroll
        for (int k = 0; k < 16; k++) {
            float af[8], bf[4];
#pragma unroll
            for (int i = 0; i < 8; i++) af[i] = As[k][ty*8 + i];
#pragma unroll
            for (int j = 0; j < 4; j++) bf[j] = Bs[k][tx*4 + j];
#pragma unroll
            for (int i = 0; i < 8; i++)
#pragma unroll
                for (int j = 0; j < 4; j++) acc[i][j] += af[i]*bf[j];
        }
        __syncthreads();
    }

#pragma unroll
    for (int i = 0; i < 8; i++) {
        int m = m0 + ty*8 + i;
        if (m >= M) continue;
#pragma unroll
        for (int j = 0; j < 4; j++) {
            int n = n0 + tx*4 + j;
            C[(size_t)m*N + n] = acc[i][j];
        }
    }
}

// ---------------------------------------------------------------------------
// FUSED edge-conv: per block, 8 points x 20 neighbors (160 rows) x 64 channels.
// Computes H = gather(feat)[row] . wa + T[point], then reduces over k in-block:
//   hmax/hmin per (point,channel), per-channel sum/sumsq (atomics, 1 pair/ch/blk)
// Never materializes H in HBM.
// ---------------------------------------------------------------------------
#define FP    8
#define FROWS (FP*KNN)      // 160
#define AS_STRIDE 168
#define BS_BASE   (16*AS_STRIDE)      // 2688
#define STG_STRIDE 66

__global__ __launch_bounds__(256)
void fused_edge_kernel(const float* __restrict__ feat,   // [BNTOT, C]
                       const float* __restrict__ wa,     // [O, C]
                       const float* __restrict__ T,      // [BNTOT, O]
                       const int* __restrict__ idx,      // [BNTOT, KNN]
                       int C, int O,
                       float* __restrict__ hmax, float* __restrict__ hmin,
                       double* __restrict__ gsum, double* __restrict__ gsum2) {
    __shared__ float pool[FROWS*STG_STRIDE];   // 10560 floats: As/Bs, later stage
    __shared__ int   sidx[FROWS];
    __shared__ float sT[FP*64];                // later reused as ss/ssq

    int tid = threadIdx.x;
    int p0  = blockIdx.x * FP;          // first point of this block
    int n0  = blockIdx.y * 64;          // channel tile

    // gather row indices (with batch base folded in)
    if (tid < FROWS) {
        int p  = tid / KNN;
        int k  = tid - p*KNN;
        int bn = p0 + p;
        sidx[tid] = (bn >> 11)*NPTS + idx[bn*KNN + k];
    }
    // T tile
    {
        int e = tid;            // 512 elems, 2 per thread
        sT[e]       = T[(size_t)(p0 + (e >> 6))*O + n0 + (e & 63)];
        e += 256;
        sT[e]       = T[(size_t)(p0 + (e >> 6))*O + n0 + (e & 63)];
    }
    __syncthreads();

    int tx = tid & 7;           // 8 col groups of 8
    int ty = tid >> 3;          // 32 row groups of 5

    float acc[5][8];
#pragma unroll
    for (int i = 0; i < 5; i++)
#pragma unroll
        for (int j = 0; j < 8; j++) acc[i][j] = 0.f;

    for (int k0 = 0; k0 < C; k0 += 16) {
        // load A (gathered): 160 x 16 = 2560 elems -> 10/thread
#pragma unroll
        for (int i = 0; i < 10; i++) {
            int e = tid + i*256;
            int c = e & 15, r = e >> 4;
            float v = 0.f;
            if (k0 + c < C) v = feat[(size_t)sidx[r]*C + k0 + c];
            pool[c*AS_STRIDE + r] = v;
        }
        // load B (weights): 64 x 16 = 1024 -> 4/thread
#pragma unroll
        for (int i = 0; i < 4; i++) {
            int e = tid + i*256;
            int c = e & 15, r = e >> 4;
            float v = 0.f;
            if (k0 + c < C) v = wa[(size_t)(n0 + r)*C + k0 + c];
            pool[BS_BASE + c*72 + r] = v;
        }
        __syncthreads();
#pragma unroll
        for (int k = 0; k < 16; k++) {
            float af[5], bf[8];
#pragma unroll
            for (int i = 0; i < 5; i++) af[i] = pool[k*AS_STRIDE + ty*5 + i];
#pragma unroll
            for (int j = 0; j < 8; j++) bf[j] = pool[BS_BASE + k*72 + tx*8 + j];
#pragma unroll
            for (int i = 0; i < 5; i++)
#pragma unroll
                for (int j = 0; j < 8; j++) acc[i][j] += af[i]*bf[j];
        }
        __syncthreads();
    }

    // add T (H = nbr.wa + T) and stage the 160x64 tile to smem
#pragma unroll
    for (int i = 0; i < 5; i++) {
        int r = ty*5 + i;
        int p = r / KNN;
#pragma unroll
        for (int j = 0; j < 8; j++) {
            float v = acc[i][j] + sT[p*64 + tx*8 + j];
            pool[r*STG_STRIDE + tx*8 + j] = v;
        }
    }
    __syncthreads();

    // phase 2: reduce over k (and accumulate channel sums)
    int ol = tid & 63;
    int gi = tid >> 6;                  // 0..3, handles points gi and gi+4
    float s = 0.f, s2 = 0.f;
#pragma unroll
    for (int half = 0; half < 2; half++) {
        int p = gi + half*4;
        float mx = -INFINITY, mn = INFINITY;
#pragma unroll
        for (int k = 0; k < KNN; k++) {
            float v = pool[(p*KNN + k)*STG_STRIDE + ol];
            mx = fmaxf(mx, v); mn = fminf(mn, v);
            s += v; s2 += v*v;
        }
        size_t oi = (size_t)(p0 + p)*O + n0 + ol;
        hmax[oi] = mx;
        hmin[oi] = mn;
    }
    // per-channel partial sums: reuse sT as ss[4][64] / ssq[4][64]
    sT[gi*64 + ol] = s;
    sT[256 + gi*64 + ol] = s2;
    __syncthreads();
    if (gi == 0) {
        float ts  = sT[ol] + sT[64+ol] + sT[128+ol] + sT[192+ol];
        float ts2 = sT[256+ol] + sT[320+ol] + sT[384+ol] + sT[448+ol];
        atomicAdd(&gsum[n0 + ol],  (double)ts);
        atomicAdd(&gsum2[n0 + ol], (double)ts2);
    }
}

// ---------------------------------------------------------------------------
// Column reduce for point convs (sum/sumsq per channel)
// ---------------------------------------------------------------------------
__global__ __launch_bounds__(256)
void colreduce_kernel(const float* __restrict__ P, int O,
                      double* __restrict__ gsum, double* __restrict__ gsum2) {
    int ol = threadIdx.x & 63;
    int gi = threadIdx.x >> 6;
    int o  = blockIdx.x*64 + ol;
    int r0 = blockIdx.y*256 + gi*64;
    float s = 0.f, s2 = 0.f;
    for (int r = r0; r < r0 + 64; r++) {
        float v = P[(size_t)r*O + o];
        s += v; s2 += v*v;
    }
    __shared__ float ss[4][64], ssq[4][64];
    ss[gi][ol] = s; ssq[gi][ol] = s2;
    __syncthreads();
    if (gi == 0) {
        atomicAdd(&gsum[o],  (double)(ss[0][ol]+ss[1][ol]+ss[2][ol]+ss[3][ol]));
        atomicAdd(&gsum2[o], (double)(ssq[0][ol]+ssq[1][ol]+ssq[2][ol]+ssq[3][ol]));
    }
}

__global__ void bn_params_kernel(const double* __restrict__ gsum, const double* __restrict__ gsum2,
                                 const float* __restrict__ g, const float* __restrict__ b,
                                 int O, double cnt,
                                 float* __restrict__ scale, float* __restrict__ shift) {
    int o = threadIdx.x;
    if (o >= O) return;
    double m   = gsum[o] / cnt;
    double var = gsum2[o] / cnt - m*m;
    float sc = g[o] * rsqrtf((float)var + BN_EPS);
    scale[o] = sc;
    shift[o] = b[o] - (float)m * sc;
}

__global__ void edge_finalize_kernel(const float* __restrict__ hmax, const float* __restrict__ hmin,
                                     const float* __restrict__ scale, const float* __restrict__ shift,
                                     float* __restrict__ out, int O) {
    int i = blockIdx.x*256 + threadIdx.x;
    if (i >= BNTOT*O) return;
    int o = i & (O - 1);                        // O is a power of two
    float sc = scale[o];
    float v = (sc >= 0.f ? hmax[i] : hmin[i]) * sc + shift[o];
    out[i] = v >= 0.f ? v : NEG_SLOPE*v;
}

// h6: act + global max over n per (b,o). grid (256/64, NB), block 256.
__global__ __launch_bounds__(256)
void h6_finalize_kernel(const float* __restrict__ P,
                        const float* __restrict__ scale, const float* __restrict__ shift,
                        float* __restrict__ gmax) {
    int ol = threadIdx.x & 63;
    int gi = threadIdx.x >> 6;
    int o = blockIdx.x*64 + ol;
    int b = blockIdx.y;
    float sc = scale[o], sh = shift[o];
    float mx = -INFINITY;
    for (int n = gi*512; n < (gi+1)*512; n++) {
        float v = P[((size_t)(b*NPTS + n))*256 + o]*sc + sh;
        v = v >= 0.f ? v : NEG_SLOPE*v;
        mx = fmaxf(mx, v);
    }
    __shared__ float sm[4][64];
    sm[gi][ol] = mx;
    __syncthreads();
    if (gi == 0)
        gmax[b*256 + o] = fmaxf(fmaxf(sm[0][ol], sm[1][ol]), fmaxf(sm[2][ol], sm[3][ol]));
}

__global__ void cat_kernel(const float* __restrict__ x1, const float* __restrict__ x2,
                           const float* __restrict__ x3, const float* __restrict__ x4,
                           const float* __restrict__ gmax, float* __restrict__ cat) {
    size_t i = (size_t)blockIdx.x*256 + threadIdx.x;
    if (i >= (size_t)BNTOT*768) return;
    int bn = (int)(i / 768);
    int c  = (int)(i - (size_t)bn*768);
    float v;
    if      (c < 64)  v = x1[bn*64  + c];
    else if (c < 128) v = x2[bn*64  + c - 64];
    else if (c < 256) v = x3[bn*128 + c - 128];
    else if (c < 512) v = x4[bn*256 + c - 256];
    else              v = gmax[(bn >> 11)*256 + c - 512];
    cat[i] = v;
}

// final: act + transpose (B,N,256) -> (B,256,N)
__global__ void out_transpose_kernel(const float* __restrict__ P,
                                     const float* __restrict__ scale, const float* __restrict__ shift,
                                     float* __restrict__ out) {
    __shared__ float tile[32][33];
    int b  = blockIdx.z;
    int n0 = blockIdx.x*32, o0 = blockIdx.y*32;
    int tx = threadIdx.x, ty = threadIdx.y;
    int o = o0 + tx;
    float v = P[((size_t)(b*NPTS + n0 + ty))*256 + o]*scale[o] + shift[o];
    v = v >= 0.f ? v : NEG_SLOPE*v;
    tile[ty][tx] = v;
    __syncthreads();
    out[(size_t)b*256*NPTS + (size_t)(o0 + ty)*NPTS + n0 + tx] = tile[tx][ty];
}

// ---------------------------------------------------------------------------
// Host side
// ---------------------------------------------------------------------------
static void* sym(const void* s) { void* p = nullptr; cudaGetSymbolAddress(&p, s); return p; }

extern "C" void kernel_launch(void* const* d_in, const int* in_sizes, int n_in,
                              void* d_out, int out_size) {
    const float* x  = (const float*)d_in[0];
    const float* W[4] = { (const float*)d_in[1], (const float*)d_in[4],
                          (const float*)d_in[7], (const float*)d_in[10] };
    const float* G[4] = { (const float*)d_in[2], (const float*)d_in[5],
                          (const float*)d_in[8], (const float*)d_in[11] };
    const float* Bb[4] = { (const float*)d_in[3], (const float*)d_in[6],
                           (const float*)d_in[9], (const float*)d_in[12] };
    const float* W6 = (const float*)d_in[13];
    const float* g6 = (const float*)d_in[14];
    const float* b6 = (const float*)d_in[15];
    const float* W5 = (const float*)d_in[16];
    const float* g5 = (const float*)d_in[17];
    const float* b5 = (const float*)d_in[18];

    float*  f0   = (float*)sym(g_f0);
    float*  x1   = (float*)sym(g_x1);
    float*  x2   = (float*)sym(g_x2);
    float*  x3   = (float*)sym(g_x3);
    float*  x4   = (float*)sym(g_x4);
    float*  pd   = (float*)sym(g_pd);
    int*    idx  = (int*)  sym(g_idx);
    float*  wa   = (float*)sym(g_wa);
    float*  wd   = (float*)sym(g_wd);
    float*  Tb   = (float*)sym(g_T);
    float*  hmax = (float*)sym(g_hmax);
    float*  hmin = (float*)sym(g_hmin);
    float*  Pb   = (float*)sym(g_P);
    float*  cat  = (float*)sym(g_cat);
    float*  gmax = (float*)sym(g_gmax);
    double* s0   = (double*)sym(g_sum);
    double* s2   = (double*)sym(g_sum2);
    float*  sc   = (float*)sym(g_scale);
    float*  sh   = (float*)sym(g_shift);

    // input transpose (B,3,N) -> (B,N,3)
    transpose_in_kernel<<<(NB*3*NPTS + 255)/256, 256>>>(x, f0);

    const float* feats[4] = { f0, x1, x2, x3 };
    float*       outs [4] = { x1, x2, x3, x4 };
    const int    Cs[4] = { 3, 64, 64, 128 };
    const int    Os[4] = { 64, 64, 128, 256 };

    for (int L = 0; L < 4; L++) {
        int C = Cs[L], O = Os[L];
        const float* feat = feats[L];

        // weights split + center term first (so layer-0 dist lands on ncu's
        // profiled launch slot: -s 5 -c 1 -> 6th launch)
        prep_w_kernel<<<(O*C + 255)/256, 256>>>(W[L], O, C, wa, wd);
        gemm_nt_kernel<<<dim3((BNTOT + 127)/128, O/64), 256>>>(feat, wd, Tb, BNTOT, O, C);
        zero_stats_kernel<<<1, 256>>>(s0, s2);
        if (L == 0) zero_stats_kernel<<<1, 256>>>(s0, s2);  // pad launch index

        // kNN: direct negative squared distance + top-20
        dim3 ggrid(NPTS/128, NPTS/64, NB);
        dist_kernel<<<ggrid, 256>>>(feat, pd, C);
        topk_kernel<<<BNTOT, 128>>>(pd, idx);

        // fused gathered GEMM + k-reduction + BN stats (no H in HBM)
        fused_edge_kernel<<<dim3(BNTOT/FP, O/64), 256>>>(
            feat, wa, Tb, idx, C, O, hmax, hmin, s0, s2);
        bn_params_kernel<<<1, 256>>>(s0, s2, G[L], Bb[L], O, (double)MEDGE, sc, sh);
        edge_finalize_kernel<<<(BNTOT*O + 255)/256, 256>>>(hmax, hmin, sc, sh, outs[L], O);
    }

    // --- point conv h6 = lrelu(bn(x4 . W6^T)), then x5 = max over n ---
    gemm_nt_kernel<<<dim3(BNTOT/128, 256/64), 256>>>(x4, W6, Pb, BNTOT, 256, 256);
    zero_stats_kernel<<<1, 256>>>(s0, s2);
    colreduce_kernel<<<dim3(256/64, BNTOT/256), 256>>>(Pb, 256, s0, s2);
    bn_params_kernel<<<1, 256>>>(s0, s2, g6, b6, 256, (double)BNTOT, sc, sh);
    h6_finalize_kernel<<<dim3(256/64, NB), 256>>>(Pb, sc, sh, gmax);

    // --- concat [x1,x2,x3,x4,x5] -> 768 ---
    cat_kernel<<<(int)(((size_t)BNTOT*768 + 255)/256), 256>>>(x1, x2, x3, x4, gmax, cat);

    // --- final point conv + transpose output ---
    gemm_nt_kernel<<<dim3(BNTOT/128, 256/64), 256>>>(cat, W5, Pb, BNTOT, 256, 768);
    zero_stats_kernel<<<1, 256>>>(s0, s2);
    colreduce_kernel<<<dim3(256/64, BNTOT/256), 256>>>(Pb, 256, s0, s2);
    bn_params_kernel<<<1, 256>>>(s0, s2, g5, b5, 256, (double)BNTOT, sc, sh);
    out_transpose_kernel<<<dim3(NPTS/32, 256/32, NB), dim3(32, 32)>>>(Pb, sc, sh, (float*)d_out);
}

// round 4
// speedup vs baseline: 1.0142x; 1.0142x over previous
#include <cuda_runtime.h>
#include <cuda_bf16.h>
#include <math.h>

// ---------------------------------------------------------------------------
// Problem constants
// ---------------------------------------------------------------------------
#define NB 8
#define NPTS 2048
#define BNTOT (NB*NPTS)          // 16384
#define KNN 20
#define MEDGE (BNTOT*KNN)        // 327680
#define NEG_SLOPE 0.2f
#define BN_EPS 1e-5f

// ---------------------------------------------------------------------------
// Scratch (device globals -- no allocation allowed)
// ---------------------------------------------------------------------------
__device__ float g_f0  [BNTOT*3];
__device__ float g_x1  [BNTOT*64];
__device__ float g_x2  [BNTOT*64];
__device__ float g_x3  [BNTOT*128];
__device__ float g_x4  [BNTOT*256];
__device__ float g_pd  [(size_t)NB*NPTS*NPTS];       // 134 MB
__device__ int   g_idx [MEDGE];
__device__ float g_wa  [256*128];
__device__ float g_wd  [256*128];
__device__ float g_T   [BNTOT*256];
__device__ float g_hmax[BNTOT*256];
__device__ float g_hmin[BNTOT*256];
__device__ float g_P   [BNTOT*256];
__device__ float g_cat [BNTOT*768];
__device__ float g_gmax[NB*256];
__device__ double g_sum [256];
__device__ double g_sum2[256];
__device__ float g_scale[256];
__device__ float g_shift[256];

// ---------------------------------------------------------------------------
// Small elementwise kernels
// ---------------------------------------------------------------------------
__global__ void transpose_in_kernel(const float* __restrict__ x, float* __restrict__ f) {
    int i = blockIdx.x*256 + threadIdx.x;                 // B*3*N = 49152
    if (i >= NB*3*NPTS) return;
    int b = i / (3*NPTS);
    int rem = i - b*3*NPTS;
    int c = rem / NPTS;
    int n = rem - c*NPTS;
    f[(b*NPTS + n)*3 + c] = x[i];
}

__global__ void prep_w_kernel(const float* __restrict__ W, int O, int C,
                              float* __restrict__ wa, float* __restrict__ wd) {
    int i = blockIdx.x*256 + threadIdx.x;
    if (i >= O*C) return;
    int o = i / C, c = i - o*C;
    float a = W[o*2*C + c];
    wa[i] = a;
    wd[i] = W[o*2*C + C + c] - a;
}

__global__ void zero_stats_kernel(double* s, double* s2) {
    int t = threadIdx.x;
    if (t < 256) { s[t] = 0.0; s2[t] = 0.0; }
}

// ---------------------------------------------------------------------------
// Direct squared-distance kernel: pd[b,i,j] = -sum_c (x_i[c]-x_j[c])^2
// ---------------------------------------------------------------------------
__global__ __launch_bounds__(256)
void dist_kernel(const float* __restrict__ feat, float* __restrict__ pd, int C) {
    __shared__ float As[16][129];
    __shared__ float Bs[16][65];
    int b  = blockIdx.z;
    const float* F = feat + (size_t)b*NPTS*C;
    int tid = threadIdx.x;
    int tx = tid & 15;         // col group
    int ty = tid >> 4;         // row group
    int m0 = blockIdx.x * 128;
    int n0 = blockIdx.y * 64;

    float acc[8][4];
#pragma unroll
    for (int i = 0; i < 8; i++)
#pragma unroll
        for (int j = 0; j < 4; j++) acc[i][j] = 0.f;

    for (int k0 = 0; k0 < C; k0 += 16) {
#pragma unroll
        for (int i = 0; i < 8; i++) {
            int e = tid + i*256;
            int c = e & 15, r = e >> 4;
            float v = 0.f;
            if (k0 + c < C) v = F[(size_t)(m0 + r)*C + k0 + c];
            As[c][r] = v;
        }
#pragma unroll
        for (int i = 0; i < 4; i++) {
            int e = tid + i*256;
            int c = e & 15, r = e >> 4;
            float v = 0.f;
            if (k0 + c < C) v = F[(size_t)(n0 + r)*C + k0 + c];
            Bs[c][r] = v;
        }
        __syncthreads();
#pragma unroll
        for (int k = 0; k < 16; k++) {
            float af[8], bf[4];
#pragma unroll
            for (int i = 0; i < 8; i++) af[i] = As[k][ty*8 + i];
#pragma unroll
            for (int j = 0; j < 4; j++) bf[j] = Bs[k][tx*4 + j];
#pragma unroll
            for (int i = 0; i < 8; i++)
#pragma unroll
                for (int j = 0; j < 4; j++) {
                    float d = af[i] - bf[j];
                    acc[i][j] = fmaf(d, d, acc[i][j]);
                }
        }
        __syncthreads();
    }

    float* pdb = pd + (size_t)b*NPTS*NPTS;
#pragma unroll
    for (int i = 0; i < 8; i++) {
        int m = m0 + ty*8 + i;
#pragma unroll
        for (int j = 0; j < 4; j++) {
            int n = n0 + tx*4 + j;
            pdb[(size_t)m*NPTS + n] = -acc[i][j];
        }
    }
}

// ---------------------------------------------------------------------------
// Top-K (K=20) per row, iterative argmax (ties -> lower index)
// ---------------------------------------------------------------------------
__global__ __launch_bounds__(128)
void topk_kernel(const float* __restrict__ pd, int* __restrict__ idx) {
    int bn = blockIdx.x;
    const float* row = pd + (size_t)bn * NPTS;
    __shared__ float v[NPTS];
    __shared__ float rv[128];
    __shared__ int   ri[128];
    int t = threadIdx.x;
    for (int j = t; j < NPTS; j += 128) v[j] = row[j];
    __syncthreads();
    for (int it = 0; it < KNN; it++) {
        float bv = -INFINITY; int bi = 0x7fffffff;
        for (int j = t; j < NPTS; j += 128) {
            float x = v[j];
            if (x > bv || (x == bv && j < bi)) { bv = x; bi = j; }
        }
        rv[t] = bv; ri[t] = bi;
        __syncthreads();
        for (int s = 64; s > 0; s >>= 1) {
            if (t < s) {
                float ov = rv[t+s]; int oi = ri[t+s];
                if (ov > rv[t] || (ov == rv[t] && oi < ri[t])) { rv[t] = ov; ri[t] = oi; }
            }
            __syncthreads();
        }
        if (t == 0) { idx[bn*KNN + it] = ri[0]; v[ri[0]] = -INFINITY; }
        __syncthreads();
    }
}

// ---------------------------------------------------------------------------
// Generic NT GEMM (used for T and the point convs):
// C[m,n] = sum_k A[m,k]*B[n,k]
// ---------------------------------------------------------------------------
__global__ __launch_bounds__(256)
void gemm_nt_kernel(const float* __restrict__ A, const float* __restrict__ B,
                    float* __restrict__ C, int M, int N, int K) {
    __shared__ float As[16][129];
    __shared__ float Bs[16][65];
    int tid = threadIdx.x;
    int tx = tid & 15;
    int ty = tid >> 4;
    int m0 = blockIdx.x * 128;
    int n0 = blockIdx.y * 64;

    float acc[8][4];
#pragma unroll
    for (int i = 0; i < 8; i++)
#pragma unroll
        for (int j = 0; j < 4; j++) acc[i][j] = 0.f;

    for (int k0 = 0; k0 < K; k0 += 16) {
#pragma unroll
        for (int i = 0; i < 8; i++) {
            int e = tid + i*256;
            int c = e & 15, r = e >> 4;
            int m = m0 + r;
            float v = 0.f;
            if (m < M && k0 + c < K) v = A[(size_t)m*K + k0 + c];
            As[c][r] = v;
        }
#pragma unroll
        for (int i = 0; i < 4; i++) {
            int e = tid + i*256;
            int c = e & 15, r = e >> 4;
            float v = 0.f;
            if (k0 + c < K) v = B[(size_t)(n0 + r)*K + k0 + c];
            Bs[c][r] = v;
        }
        __syncthreads();
#pragma unroll
        for (int k = 0; k < 16; k++) {
            float af[8], bf[4];
#pragma unroll
            for (int i = 0; i < 8; i++) af[i] = As[k][ty*8 + i];
#pragma unroll
            for (int j = 0; j < 4; j++) bf[j] = Bs[k][tx*4 + j];
#pragma unroll
            for (int i = 0; i < 8; i++)
#pragma unroll
                for (int j = 0; j < 4; j++) acc[i][j] += af[i]*bf[j];
        }
        __syncthreads();
    }

#pragma unroll
    for (int i = 0; i < 8; i++) {
        int m = m0 + ty*8 + i;
        if (m >= M) continue;
#pragma unroll
        for (int j = 0; j < 4; j++) {
            int n = n0 + tx*4 + j;
            C[(size_t)m*N + n] = acc[i][j];
        }
    }
}

// ---------------------------------------------------------------------------
// FUSED edge-conv: per block, 8 points x 20 neighbors (160 rows) x 64 channels.
// Computes H = gather(feat)[row] . wa + T[point], then reduces over k in-block.
// Conflict-free smem strides: A stride 161 (==1 mod 32), B stride 68 with
// 16B-aligned rows (bf loaded as float4).
// ---------------------------------------------------------------------------
#define FP    8
#define FROWS (FP*KNN)            // 160
#define AS_STRIDE 161             // 161 % 32 == 1  -> conflict-free
#define BS_BASE   (16*AS_STRIDE)  // 2576 floats (16B aligned: 2576*4 % 16 == 0)
#define BS_STRIDE 68              // 68*4 = 272 bytes, 16B aligned rows
#define STG_STRIDE 66

__global__ __launch_bounds__(256)
void fused_edge_kernel(const float* __restrict__ feat,   // [BNTOT, C]
                       const float* __restrict__ wa,     // [O, C]
                       const float* __restrict__ T,      // [BNTOT, O]
                       const int* __restrict__ idx,      // [BNTOT, KNN]
                       int C, int O,
                       float* __restrict__ hmax, float* __restrict__ hmin,
                       double* __restrict__ gsum, double* __restrict__ gsum2) {
    __shared__ float pool[FROWS*STG_STRIDE];   // 10560 floats; phase1: A(2576)+B(1088)
    __shared__ int   sidx[FROWS];
    __shared__ float sT[FP*64];                // later reused as ss/ssq

    int tid = threadIdx.x;
    int p0  = blockIdx.x * FP;          // first point of this block
    int n0  = blockIdx.y * 64;          // channel tile

    // gather row indices (with batch base folded in)
    if (tid < FROWS) {
        int p  = tid / KNN;
        int k  = tid - p*KNN;
        int bn = p0 + p;
        sidx[tid] = (bn >> 11)*NPTS + idx[bn*KNN + k];
    }
    // T tile
    {
        int e = tid;            // 512 elems, 2 per thread
        sT[e] = T[(size_t)(p0 + (e >> 6))*O + n0 + (e & 63)];
        e += 256;
        sT[e] = T[(size_t)(p0 + (e >> 6))*O + n0 + (e & 63)];
    }
    __syncthreads();

    int tx = tid & 7;           // 8 col groups of 8
    int ty = tid >> 3;          // 32 row groups of 5

    float acc[5][8];
#pragma unroll
    for (int i = 0; i < 5; i++)
#pragma unroll
        for (int j = 0; j < 8; j++) acc[i][j] = 0.f;

    for (int k0 = 0; k0 < C; k0 += 16) {
        // load A (gathered): 160 x 16 = 2560 elems -> 10/thread
#pragma unroll
        for (int i = 0; i < 10; i++) {
            int e = tid + i*256;
            int c = e & 15, r = e >> 4;
            float v = 0.f;
            if (k0 + c < C) v = feat[(size_t)sidx[r]*C + k0 + c];
            pool[c*AS_STRIDE + r] = v;
        }
        // load B (weights): 64 x 16 = 1024 -> 4/thread
#pragma unroll
        for (int i = 0; i < 4; i++) {
            int e = tid + i*256;
            int c = e & 15, r = e >> 4;
            float v = 0.f;
            if (k0 + c < C) v = wa[(size_t)(n0 + r)*C + k0 + c];
            pool[BS_BASE + c*BS_STRIDE + r] = v;
        }
        __syncthreads();
#pragma unroll
        for (int k = 0; k < 16; k++) {
            float af[5];
#pragma unroll
            for (int i = 0; i < 5; i++) af[i] = pool[k*AS_STRIDE + ty*5 + i];
            const float4* bp = (const float4*)&pool[BS_BASE + k*BS_STRIDE + tx*8];
            float4 b0 = bp[0], b1 = bp[1];
            float bf[8] = { b0.x, b0.y, b0.z, b0.w, b1.x, b1.y, b1.z, b1.w };
#pragma unroll
            for (int i = 0; i < 5; i++)
#pragma unroll
                for (int j = 0; j < 8; j++) acc[i][j] += af[i]*bf[j];
        }
        __syncthreads();
    }

    // add T (H = nbr.wa + T) and stage the 160x64 tile to smem
#pragma unroll
    for (int i = 0; i < 5; i++) {
        int r = ty*5 + i;
        int p = r / KNN;
#pragma unroll
        for (int j = 0; j < 8; j++) {
            float v = acc[i][j] + sT[p*64 + tx*8 + j];
            pool[r*STG_STRIDE + tx*8 + j] = v;
        }
    }
    __syncthreads();

    // phase 2: reduce over k (and accumulate channel sums)
    int ol = tid & 63;
    int gi = tid >> 6;                  // 0..3, handles points gi and gi+4
    float s = 0.f, s2 = 0.f;
#pragma unroll
    for (int half = 0; half < 2; half++) {
        int p = gi + half*4;
        float mx = -INFINITY, mn = INFINITY;
#pragma unroll
        for (int k = 0; k < KNN; k++) {
            float v = pool[(p*KNN + k)*STG_STRIDE + ol];
            mx = fmaxf(mx, v); mn = fminf(mn, v);
            s += v; s2 += v*v;
        }
        size_t oi = (size_t)(p0 + p)*O + n0 + ol;
        hmax[oi] = mx;
        hmin[oi] = mn;
    }
    __syncthreads();
    // per-channel partial sums: reuse sT as ss[4][64] / ssq[4][64]
    sT[gi*64 + ol] = s;
    sT[256 + gi*64 + ol] = s2;
    __syncthreads();
    if (gi == 0) {
        float ts  = sT[ol] + sT[64+ol] + sT[128+ol] + sT[192+ol];
        float ts2 = sT[256+ol] + sT[320+ol] + sT[384+ol] + sT[448+ol];
        atomicAdd(&gsum[n0 + ol],  (double)ts);
        atomicAdd(&gsum2[n0 + ol], (double)ts2);
    }
}

// ---------------------------------------------------------------------------
// Column reduce for point convs (sum/sumsq per channel)
// ---------------------------------------------------------------------------
__global__ __launch_bounds__(256)
void colreduce_kernel(const float* __restrict__ P, int O,
                      double* __restrict__ gsum, double* __restrict__ gsum2) {
    int ol = threadIdx.x & 63;
    int gi = threadIdx.x >> 6;
    int o  = blockIdx.x*64 + ol;
    int r0 = blockIdx.y*256 + gi*64;
    float s = 0.f, s2 = 0.f;
    for (int r = r0; r < r0 + 64; r++) {
        float v = P[(size_t)r*O + o];
        s += v; s2 += v*v;
    }
    __shared__ float ss[4][64], ssq[4][64];
    ss[gi][ol] = s; ssq[gi][ol] = s2;
    __syncthreads();
    if (gi == 0) {
        atomicAdd(&gsum[o],  (double)(ss[0][ol]+ss[1][ol]+ss[2][ol]+ss[3][ol]));
        atomicAdd(&gsum2[o], (double)(ssq[0][ol]+ssq[1][ol]+ssq[2][ol]+ssq[3][ol]));
    }
}

__global__ void bn_params_kernel(const double* __restrict__ gsum, const double* __restrict__ gsum2,
                                 const float* __restrict__ g, const float* __restrict__ b,
                                 int O, double cnt,
                                 float* __restrict__ scale, float* __restrict__ shift) {
    int o = threadIdx.x;
    if (o >= O) return;
    double m   = gsum[o] / cnt;
    double var = gsum2[o] / cnt - m*m;
    float sc = g[o] * rsqrtf((float)var + BN_EPS);
    scale[o] = sc;
    shift[o] = b[o] - (float)m * sc;
}

__global__ void edge_finalize_kernel(const float* __restrict__ hmax, const float* __restrict__ hmin,
                                     const float* __restrict__ scale, const float* __restrict__ shift,
                                     float* __restrict__ out, int O) {
    int i = blockIdx.x*256 + threadIdx.x;
    if (i >= BNTOT*O) return;
    int o = i & (O - 1);                        // O is a power of two
    float sc = scale[o];
    float v = (sc >= 0.f ? hmax[i] : hmin[i]) * sc + shift[o];
    out[i] = v >= 0.f ? v : NEG_SLOPE*v;
}

// h6: act + global max over n per (b,o). grid (256/64, NB), block 256.
__global__ __launch_bounds__(256)
void h6_finalize_kernel(const float* __restrict__ P,
                        const float* __restrict__ scale, const float* __restrict__ shift,
                        float* __restrict__ gmax) {
    int ol = threadIdx.x & 63;
    int gi = threadIdx.x >> 6;
    int o = blockIdx.x*64 + ol;
    int b = blockIdx.y;
    float sc = scale[o], sh = shift[o];
    float mx = -INFINITY;
    for (int n = gi*512; n < (gi+1)*512; n++) {
        float v = P[((size_t)(b*NPTS + n))*256 + o]*sc + sh;
        v = v >= 0.f ? v : NEG_SLOPE*v;
        mx = fmaxf(mx, v);
    }
    __shared__ float sm[4][64];
    sm[gi][ol] = mx;
    __syncthreads();
    if (gi == 0)
        gmax[b*256 + o] = fmaxf(fmaxf(sm[0][ol], sm[1][ol]), fmaxf(sm[2][ol], sm[3][ol]));
}

__global__ void cat_kernel(const float* __restrict__ x1, const float* __restrict__ x2,
                           const float* __restrict__ x3, const float* __restrict__ x4,
                           const float* __restrict__ gmax, float* __restrict__ cat) {
    size_t i = (size_t)blockIdx.x*256 + threadIdx.x;
    if (i >= (size_t)BNTOT*768) return;
    int bn = (int)(i / 768);
    int c  = (int)(i - (size_t)bn*768);
    float v;
    if      (c < 64)  v = x1[bn*64  + c];
    else if (c < 128) v = x2[bn*64  + c - 64];
    else if (c < 256) v = x3[bn*128 + c - 128];
    else if (c < 512) v = x4[bn*256 + c - 256];
    else              v = gmax[(bn >> 11)*256 + c - 512];
    cat[i] = v;
}

// final: act + transpose (B,N,256) -> (B,256,N)
__global__ void out_transpose_kernel(const float* __restrict__ P,
                                     const float* __restrict__ scale, const float* __restrict__ shift,
                                     float* __restrict__ out) {
    __shared__ float tile[32][33];
    int b  = blockIdx.z;
    int n0 = blockIdx.x*32, o0 = blockIdx.y*32;
    int tx = threadIdx.x, ty = threadIdx.y;
    int o = o0 + tx;
    float v = P[((size_t)(b*NPTS + n0 + ty))*256 + o]*scale[o] + shift[o];
    v = v >= 0.f ? v : NEG_SLOPE*v;
    tile[ty][tx] = v;
    __syncthreads();
    out[(size_t)b*256*NPTS + (size_t)(o0 + ty)*NPTS + n0 + tx] = tile[tx][ty];
}

// ---------------------------------------------------------------------------
// Host side
// ---------------------------------------------------------------------------
static void* sym(const void* s) { void* p = nullptr; cudaGetSymbolAddress(&p, s); return p; }

extern "C" void kernel_launch(void* const* d_in, const int* in_sizes, int n_in,
                              void* d_out, int out_size) {
    const float* x  = (const float*)d_in[0];
    const float* W[4] = { (const float*)d_in[1], (const float*)d_in[4],
                          (const float*)d_in[7], (const float*)d_in[10] };
    const float* G[4] = { (const float*)d_in[2], (const float*)d_in[5],
                          (const float*)d_in[8], (const float*)d_in[11] };
    const float* Bb[4] = { (const float*)d_in[3], (const float*)d_in[6],
                           (const float*)d_in[9], (const float*)d_in[12] };
    const float* W6 = (const float*)d_in[13];
    const float* g6 = (const float*)d_in[14];
    const float* b6 = (const float*)d_in[15];
    const float* W5 = (const float*)d_in[16];
    const float* g5 = (const float*)d_in[17];
    const float* b5 = (const float*)d_in[18];

    float*  f0   = (float*)sym(g_f0);
    float*  x1   = (float*)sym(g_x1);
    float*  x2   = (float*)sym(g_x2);
    float*  x3   = (float*)sym(g_x3);
    float*  x4   = (float*)sym(g_x4);
    float*  pd   = (float*)sym(g_pd);
    int*    idx  = (int*)  sym(g_idx);
    float*  wa   = (float*)sym(g_wa);
    float*  wd   = (float*)sym(g_wd);
    float*  Tb   = (float*)sym(g_T);
    float*  hmax = (float*)sym(g_hmax);
    float*  hmin = (float*)sym(g_hmin);
    float*  Pb   = (float*)sym(g_P);
    float*  cat  = (float*)sym(g_cat);
    float*  gmax = (float*)sym(g_gmax);
    double* s0   = (double*)sym(g_sum);
    double* s2   = (double*)sym(g_sum2);
    float*  sc   = (float*)sym(g_scale);
    float*  sh   = (float*)sym(g_shift);

    // input transpose (B,3,N) -> (B,N,3)
    transpose_in_kernel<<<(NB*3*NPTS + 255)/256, 256>>>(x, f0);

    const float* feats[4] = { f0, x1, x2, x3 };
    float*       outs [4] = { x1, x2, x3, x4 };
    const int    Cs[4] = { 3, 64, 64, 128 };
    const int    Os[4] = { 64, 64, 128, 256 };

    for (int L = 0; L < 4; L++) {
        int C = Cs[L], O = Os[L];
        const float* feat = feats[L];

        // kNN: direct negative squared distance + top-20
        dim3 ggrid(NPTS/128, NPTS/64, NB);
        dist_kernel<<<ggrid, 256>>>(feat, pd, C);
        topk_kernel<<<BNTOT, 128>>>(pd, idx);

        // weights split + center term
        prep_w_kernel<<<(O*C + 255)/256, 256>>>(W[L], O, C, wa, wd);
        gemm_nt_kernel<<<dim3((BNTOT + 127)/128, O/64), 256>>>(feat, wd, Tb, BNTOT, O, C);
        zero_stats_kernel<<<1, 256>>>(s0, s2);

        // fused gathered GEMM + k-reduction + BN stats (no H in HBM)
        fused_edge_kernel<<<dim3(BNTOT/FP, O/64), 256>>>(
            feat, wa, Tb, idx, C, O, hmax, hmin, s0, s2);
        bn_params_kernel<<<1, 256>>>(s0, s2, G[L], Bb[L], O, (double)MEDGE, sc, sh);
        edge_finalize_kernel<<<(BNTOT*O + 255)/256, 256>>>(hmax, hmin, sc, sh, outs[L], O);
    }

    // --- point conv h6 = lrelu(bn(x4 . W6^T)), then x5 = max over n ---
    gemm_nt_kernel<<<dim3(BNTOT/128, 256/64), 256>>>(x4, W6, Pb, BNTOT, 256, 256);
    zero_stats_kernel<<<1, 256>>>(s0, s2);
    colreduce_kernel<<<dim3(256/64, BNTOT/256), 256>>>(Pb, 256, s0, s2);
    bn_params_kernel<<<1, 256>>>(s0, s2, g6, b6, 256, (double)BNTOT, sc, sh);
    h6_finalize_kernel<<<dim3(256/64, NB), 256>>>(Pb, sc, sh, gmax);

    // --- concat [x1,x2,x3,x4,x5] -> 768 ---
    cat_kernel<<<(int)(((size_t)BNTOT*768 + 255)/256), 256>>>(x1, x2, x3, x4, gmax, cat);

    // --- final point conv + transpose output ---
    gemm_nt_kernel<<<dim3(BNTOT/128, 256/64), 256>>>(cat, W5, Pb, BNTOT, 256, 768);
    zero_stats_kernel<<<1, 256>>>(s0, s2);
    colreduce_kernel<<<dim3(256/64, BNTOT/256), 256>>>(Pb, 256, s0, s2);
    bn_params_kernel<<<1, 256>>>(s0, s2, g5, b5, 256, (double)BNTOT, sc, sh);
    out_transpose_kernel<<<dim3(NPTS/32, 256/32, NB), dim3(32, 32)>>>(Pb, sc, sh, (float*)d_out);
}

// round 6
// speedup vs baseline: 1.1084x; 1.0929x over previous
#include <cuda_runtime.h>
#include <cuda_bf16.h>
#include <math.h>

// ---------------------------------------------------------------------------
// Problem constants
// ---------------------------------------------------------------------------
#define NB 8
#define NPTS 2048
#define BNTOT (NB*NPTS)          // 16384
#define KNN 20
#define MEDGE (BNTOT*KNN)        // 327680
#define NEG_SLOPE 0.2f
#define BN_EPS 1e-5f
#define NT 16                    // 2048/128 tiles per dim
#define NPAIRS (NT*(NT+1)/2)     // 136

// ---------------------------------------------------------------------------
// Scratch (device globals -- no allocation allowed)
// ---------------------------------------------------------------------------
__device__ float g_f0  [BNTOT*3];
__device__ float g_x1  [BNTOT*64];
__device__ float g_x2  [BNTOT*64];
__device__ float g_x3  [BNTOT*128];
__device__ float g_x4  [BNTOT*256];
__device__ float g_pd  [(size_t)NB*NPTS*NPTS];       // 134 MB
__device__ int   g_idx [MEDGE];
__device__ float g_wa  [256*128];
__device__ float g_wd  [256*128];
__device__ float g_T   [BNTOT*256];
__device__ float g_hmax[BNTOT*256];
__device__ float g_hmin[BNTOT*256];
__device__ float g_P   [BNTOT*256];
__device__ float g_cat [BNTOT*768];
__device__ float g_gmax[NB*256];
__device__ double g_sum [256];
__device__ double g_sum2[256];
__device__ float g_scale[256];
__device__ float g_shift[256];

// ---------------------------------------------------------------------------
// Small elementwise kernels
// ---------------------------------------------------------------------------
__global__ void transpose_in_kernel(const float* __restrict__ x, float* __restrict__ f) {
    int i = blockIdx.x*256 + threadIdx.x;                 // B*3*N = 49152
    if (i >= NB*3*NPTS) return;
    int b = i / (3*NPTS);
    int rem = i - b*3*NPTS;
    int c = rem / NPTS;
    int n = rem - c*NPTS;
    f[(b*NPTS + n)*3 + c] = x[i];
}

__global__ void prep_w_kernel(const float* __restrict__ W, int O, int C,
                              float* __restrict__ wa, float* __restrict__ wd) {
    int i = blockIdx.x*256 + threadIdx.x;
    if (i >= O*C) return;
    int o = i / C, c = i - o*C;
    float a = W[o*2*C + c];
    wa[i] = a;
    wd[i] = W[o*2*C + C + c] - a;
}

__global__ void zero_stats_kernel(double* s, double* s2) {
    int t = threadIdx.x;
    if (t < 256) { s[t] = 0.0; s2[t] = 0.0; }
}

// ---------------------------------------------------------------------------
// SYMMETRIC squared-distance kernel: pd[b,i,j] = -sum_c (x_i[c]-x_j[c])^2
// Only upper-triangular 128x128 tile pairs are computed; each off-diagonal
// tile is written twice (direct + transposed). (a-b)^2 is exactly symmetric
// in fp32 and the k-order is unchanged -> pd bitwise identical to the full
// computation.
// 256 threads, 8x8 micro-tile.
// ---------------------------------------------------------------------------
template<int KS>
__global__ __launch_bounds__(256)
void dist_sym_kernel(const float* __restrict__ feat, float* __restrict__ pd, int C) {
    __shared__ float As[KS][132];
    __shared__ float Bs[KS][132];
    int b = blockIdx.z;
    // decode pair index -> (ti, tj), ti <= tj
    int Lp = blockIdx.x;
    int ti = 0;
    while (Lp >= NT - ti) { Lp -= NT - ti; ti++; }
    int tj = ti + Lp;
    int m0 = ti*128, n0 = tj*128;
    bool diag = (ti == tj);

    const float* F = feat + (size_t)b*NPTS*C;
    int tid = threadIdx.x;
    int tx = tid & 15, ty = tid >> 4;

    float acc[8][8];
#pragma unroll
    for (int i = 0; i < 8; i++)
#pragma unroll
        for (int j = 0; j < 8; j++) acc[i][j] = 0.f;

    for (int k0 = 0; k0 < C; k0 += KS) {
        // load 128 x KS for both row-tile and col-tile
#pragma unroll
        for (int e = tid; e < 128*KS; e += 256) {
            int c = e % KS, r = e / KS;
            float va = 0.f, vb = 0.f;
            if (k0 + c < C) {
                va = F[(size_t)(m0 + r)*C + k0 + c];
                vb = F[(size_t)(n0 + r)*C + k0 + c];
            }
            As[c][r] = va;
            Bs[c][r] = vb;
        }
        __syncthreads();
#pragma unroll
        for (int k = 0; k < KS; k++) {
            float af[8], bf[8];
#pragma unroll
            for (int i = 0; i < 8; i++) af[i] = As[k][ty*8 + i];
#pragma unroll
            for (int j = 0; j < 8; j++) bf[j] = Bs[k][tx*8 + j];
#pragma unroll
            for (int i = 0; i < 8; i++)
#pragma unroll
                for (int j = 0; j < 8; j++) {
                    float d = af[i] - bf[j];
                    acc[i][j] = fmaf(d, d, acc[i][j]);
                }
        }
        __syncthreads();
    }

    float* pdb = pd + (size_t)b*NPTS*NPTS;
    // direct tile write: rows m, cols n (vectorized)
#pragma unroll
    for (int i = 0; i < 8; i++) {
        int m = m0 + ty*8 + i;
        float4 w0 = make_float4(-acc[i][0], -acc[i][1], -acc[i][2], -acc[i][3]);
        float4 w1 = make_float4(-acc[i][4], -acc[i][5], -acc[i][6], -acc[i][7]);
        float4* dst = (float4*)&pdb[(size_t)m*NPTS + n0 + tx*8];
        dst[0] = w0;
        dst[1] = w1;
    }
    if (!diag) {
        // transposed tile write: rows n, cols m
#pragma unroll
        for (int j = 0; j < 8; j++) {
            int n = n0 + tx*8 + j;
            float4 w0 = make_float4(-acc[0][j], -acc[1][j], -acc[2][j], -acc[3][j]);
            float4 w1 = make_float4(-acc[4][j], -acc[5][j], -acc[6][j], -acc[7][j]);
            float4* dst = (float4*)&pdb[(size_t)n*NPTS + m0 + ty*8];
            dst[0] = w0;
            dst[1] = w1;
        }
    }
}

// ---------------------------------------------------------------------------
// Top-K (K=20) per row, iterative argmax (ties -> lower index)
// ---------------------------------------------------------------------------
__global__ __launch_bounds__(128)
void topk_kernel(const float* __restrict__ pd, int* __restrict__ idx) {
    int bn = blockIdx.x;
    const float* row = pd + (size_t)bn * NPTS;
    __shared__ float v[NPTS];
    __shared__ float rv[128];
    __shared__ int   ri[128];
    int t = threadIdx.x;
    for (int j = t; j < NPTS; j += 128) v[j] = row[j];
    __syncthreads();
    for (int it = 0; it < KNN; it++) {
        float bv = -INFINITY; int bi = 0x7fffffff;
        for (int j = t; j < NPTS; j += 128) {
            float x = v[j];
            if (x > bv || (x == bv && j < bi)) { bv = x; bi = j; }
        }
        rv[t] = bv; ri[t] = bi;
        __syncthreads();
        for (int s = 64; s > 0; s >>= 1) {
            if (t < s) {
                float ov = rv[t+s]; int oi = ri[t+s];
                if (ov > rv[t] || (ov == rv[t] && oi < ri[t])) { rv[t] = ov; ri[t] = oi; }
            }
            __syncthreads();
        }
        if (t == 0) { idx[bn*KNN + it] = ri[0]; v[ri[0]] = -INFINITY; }
        __syncthreads();
    }
}

// ---------------------------------------------------------------------------
// Generic NT GEMM (used for T and the point convs):
// C[m,n] = sum_k A[m,k]*B[n,k]
// ---------------------------------------------------------------------------
__global__ __launch_bounds__(256)
void gemm_nt_kernel(const float* __restrict__ A, const float* __restrict__ B,
                    float* __restrict__ C, int M, int N, int K) {
    __shared__ float As[16][129];
    __shared__ float Bs[16][65];
    int tid = threadIdx.x;
    int tx = tid & 15;
    int ty = tid >> 4;
    int m0 = blockIdx.x * 128;
    int n0 = blockIdx.y * 64;

    float acc[8][4];
#pragma unroll
    for (int i = 0; i < 8; i++)
#pragma unroll
        for (int j = 0; j < 4; j++) acc[i][j] = 0.f;

    for (int k0 = 0; k0 < K; k0 += 16) {
#pragma unroll
        for (int i = 0; i < 8; i++) {
            int e = tid + i*256;
            int c = e & 15, r = e >> 4;
            int m = m0 + r;
            float v = 0.f;
            if (m < M && k0 + c < K) v = A[(size_t)m*K + k0 + c];
            As[c][r] = v;
        }
#pragma unroll
        for (int i = 0; i < 4; i++) {
            int e = tid + i*256;
            int c = e & 15, r = e >> 4;
            float v = 0.f;
            if (k0 + c < K) v = B[(size_t)(n0 + r)*K + k0 + c];
            Bs[c][r] = v;
        }
        __syncthreads();
#pragma unroll
        for (int k = 0; k < 16; k++) {
            float af[8], bf[4];
#pragma unroll
            for (int i = 0; i < 8; i++) af[i] = As[k][ty*8 + i];
#pragma unroll
            for (int j = 0; j < 4; j++) bf[j] = Bs[k][tx*4 + j];
#pragma unroll
            for (int i = 0; i < 8; i++)
#pragma unroll
                for (int j = 0; j < 4; j++) acc[i][j] += af[i]*bf[j];
        }
        __syncthreads();
    }

#pragma unroll
    for (int i = 0; i < 8; i++) {
        int m = m0 + ty*8 + i;
        if (m >= M) continue;
#pragma unroll
        for (int j = 0; j < 4; j++) {
            int n = n0 + tx*4 + j;
            C[(size_t)m*N + n] = acc[i][j];
        }
    }
}

// ---------------------------------------------------------------------------
// FUSED edge-conv: per block, 8 points x 20 neighbors (160 rows) x 64 channels.
// H = gather(feat)[row] . wa + T[point]; reduces over k in-block.
// ---------------------------------------------------------------------------
#define FP    8
#define FROWS (FP*KNN)            // 160
#define AS_STRIDE 161             // 161 % 32 == 1  -> conflict-free
#define BS_BASE   (16*AS_STRIDE)  // 2576 floats (16B aligned)
#define BS_STRIDE 68              // rows 16B aligned
#define STG_STRIDE 66

__global__ __launch_bounds__(256)
void fused_edge_kernel(const float* __restrict__ feat,   // [BNTOT, C]
                       const float* __restrict__ wa,     // [O, C]
                       const float* __restrict__ T,      // [BNTOT, O]
                       const int* __restrict__ idx,      // [BNTOT, KNN]
                       int C, int O,
                       float* __restrict__ hmax, float* __restrict__ hmin,
                       double* __restrict__ gsum, double* __restrict__ gsum2) {
    __shared__ float pool[FROWS*STG_STRIDE];   // 10560 floats
    __shared__ int   sidx[FROWS];
    __shared__ float sT[FP*64];

    int tid = threadIdx.x;
    int p0  = blockIdx.x * FP;
    int n0  = blockIdx.y * 64;

    if (tid < FROWS) {
        int p  = tid / KNN;
        int k  = tid - p*KNN;
        int bn = p0 + p;
        sidx[tid] = (bn >> 11)*NPTS + idx[bn*KNN + k];
    }
    {
        int e = tid;
        sT[e] = T[(size_t)(p0 + (e >> 6))*O + n0 + (e & 63)];
        e += 256;
        sT[e] = T[(size_t)(p0 + (e >> 6))*O + n0 + (e & 63)];
    }
    __syncthreads();

    int tx = tid & 7;
    int ty = tid >> 3;

    float acc[5][8];
#pragma unroll
    for (int i = 0; i < 5; i++)
#pragma unroll
        for (int j = 0; j < 8; j++) acc[i][j] = 0.f;

    for (int k0 = 0; k0 < C; k0 += 16) {
#pragma unroll
        for (int i = 0; i < 10; i++) {
            int e = tid + i*256;
            int c = e & 15, r = e >> 4;
            float v = 0.f;
            if (k0 + c < C) v = feat[(size_t)sidx[r]*C + k0 + c];
            pool[c*AS_STRIDE + r] = v;
        }
#pragma unroll
        for (int i = 0; i < 4; i++) {
            int e = tid + i*256;
            int c = e & 15, r = e >> 4;
            float v = 0.f;
            if (k0 + c < C) v = wa[(size_t)(n0 + r)*C + k0 + c];
            pool[BS_BASE + c*BS_STRIDE + r] = v;
        }
        __syncthreads();
#pragma unroll
        for (int k = 0; k < 16; k++) {
            float af[5];
#pragma unroll
            for (int i = 0; i < 5; i++) af[i] = pool[k*AS_STRIDE + ty*5 + i];
            const float4* bp = (const float4*)&pool[BS_BASE + k*BS_STRIDE + tx*8];
            float4 b0 = bp[0], b1 = bp[1];
            float bf[8] = { b0.x, b0.y, b0.z, b0.w, b1.x, b1.y, b1.z, b1.w };
#pragma unroll
            for (int i = 0; i < 5; i++)
#pragma unroll
                for (int j = 0; j < 8; j++) acc[i][j] += af[i]*bf[j];
        }
        __syncthreads();
    }

#pragma unroll
    for (int i = 0; i < 5; i++) {
        int r = ty*5 + i;
        int p = r / KNN;
#pragma unroll
        for (int j = 0; j < 8; j++) {
            float v = acc[i][j] + sT[p*64 + tx*8 + j];
            pool[r*STG_STRIDE + tx*8 + j] = v;
        }
    }
    __syncthreads();

    int ol = tid & 63;
    int gi = tid >> 6;
    float s = 0.f, s2 = 0.f;
#pragma unroll
    for (int half = 0; half < 2; half++) {
        int p = gi + half*4;
        float mx = -INFINITY, mn = INFINITY;
#pragma unroll
        for (int k = 0; k < KNN; k++) {
            float v = pool[(p*KNN + k)*STG_STRIDE + ol];
            mx = fmaxf(mx, v); mn = fminf(mn, v);
            s += v; s2 += v*v;
        }
        size_t oi = (size_t)(p0 + p)*O + n0 + ol;
        hmax[oi] = mx;
        hmin[oi] = mn;
    }
    __syncthreads();
    sT[gi*64 + ol] = s;
    sT[256 + gi*64 + ol] = s2;
    __syncthreads();
    if (gi == 0) {
        float ts  = sT[ol] + sT[64+ol] + sT[128+ol] + sT[192+ol];
        float ts2 = sT[256+ol] + sT[320+ol] + sT[384+ol] + sT[448+ol];
        atomicAdd(&gsum[n0 + ol],  (double)ts);
        atomicAdd(&gsum2[n0 + ol], (double)ts2);
    }
}

// ---------------------------------------------------------------------------
// Column reduce for point convs (sum/sumsq per channel)
// ---------------------------------------------------------------------------
__global__ __launch_bounds__(256)
void colreduce_kernel(const float* __restrict__ P, int O,
                      double* __restrict__ gsum, double* __restrict__ gsum2) {
    int ol = threadIdx.x & 63;
    int gi = threadIdx.x >> 6;
    int o  = blockIdx.x*64 + ol;
    int r0 = blockIdx.y*256 + gi*64;
    float s = 0.f, s2 = 0.f;
    for (int r = r0; r < r0 + 64; r++) {
        float v = P[(size_t)r*O + o];
        s += v; s2 += v*v;
    }
    __shared__ float ss[4][64], ssq[4][64];
    ss[gi][ol] = s; ssq[gi][ol] = s2;
    __syncthreads();
    if (gi == 0) {
        atomicAdd(&gsum[o],  (double)(ss[0][ol]+ss[1][ol]+ss[2][ol]+ss[3][ol]));
        atomicAdd(&gsum2[o], (double)(ssq[0][ol]+ssq[1][ol]+ssq[2][ol]+ssq[3][ol]));
    }
}

__global__ void bn_params_kernel(const double* __restrict__ gsum, const double* __restrict__ gsum2,
                                 const float* __restrict__ g, const float* __restrict__ b,
                                 int O, double cnt,
                                 float* __restrict__ scale, float* __restrict__ shift) {
    int o = threadIdx.x;
    if (o >= O) return;
    double m   = gsum[o] / cnt;
    double var = gsum2[o] / cnt - m*m;
    float sc = g[o] * rsqrtf((float)var + BN_EPS);
    scale[o] = sc;
    shift[o] = b[o] - (float)m * sc;
}

__global__ void edge_finalize_kernel(const float* __restrict__ hmax, const float* __restrict__ hmin,
                                     const float* __restrict__ scale, const float* __restrict__ shift,
                                     float* __restrict__ out, int O) {
    int i = blockIdx.x*256 + threadIdx.x;
    if (i >= BNTOT*O) return;
    int o = i & (O - 1);
    float sc = scale[o];
    float v = (sc >= 0.f ? hmax[i] : hmin[i]) * sc + shift[o];
    out[i] = v >= 0.f ? v : NEG_SLOPE*v;
}

// h6: act + global max over n per (b,o)
__global__ __launch_bounds__(256)
void h6_finalize_kernel(const float* __restrict__ P,
                        const float* __restrict__ scale, const float* __restrict__ shift,
                        float* __restrict__ gmax) {
    int ol = threadIdx.x & 63;
    int gi = threadIdx.x >> 6;
    int o = blockIdx.x*64 + ol;
    int b = blockIdx.y;
    float sc = scale[o], sh = shift[o];
    float mx = -INFINITY;
    for (int n = gi*512; n < (gi+1)*512; n++) {
        float v = P[((size_t)(b*NPTS + n))*256 + o]*sc + sh;
        v = v >= 0.f ? v : NEG_SLOPE*v;
        mx = fmaxf(mx, v);
    }
    __shared__ float sm[4][64];
    sm[gi][ol] = mx;
    __syncthreads();
    if (gi == 0)
        gmax[b*256 + o] = fmaxf(fmaxf(sm[0][ol], sm[1][ol]), fmaxf(sm[2][ol], sm[3][ol]));
}

__global__ void cat_kernel(const float* __restrict__ x1, const float* __restrict__ x2,
                           const float* __restrict__ x3, const float* __restrict__ x4,
                           const float* __restrict__ gmax, float* __restrict__ cat) {
    size_t i = (size_t)blockIdx.x*256 + threadIdx.x;
    if (i >= (size_t)BNTOT*768) return;
    int bn = (int)(i / 768);
    int c  = (int)(i - (size_t)bn*768);
    float v;
    if      (c < 64)  v = x1[bn*64  + c];
    else if (c < 128) v = x2[bn*64  + c - 64];
    else if (c < 256) v = x3[bn*128 + c - 128];
    else if (c < 512) v = x4[bn*256 + c - 256];
    else              v = gmax[(bn >> 11)*256 + c - 512];
    cat[i] = v;
}

// final: act + transpose (B,N,256) -> (B,256,N)
__global__ void out_transpose_kernel(const float* __restrict__ P,
                                     const float* __restrict__ scale, const float* __restrict__ shift,
                                     float* __restrict__ out) {
    __shared__ float tile[32][33];
    int b  = blockIdx.z;
    int n0 = blockIdx.x*32, o0 = blockIdx.y*32;
    int tx = threadIdx.x, ty = threadIdx.y;
    int o = o0 + tx;
    float v = P[((size_t)(b*NPTS + n0 + ty))*256 + o]*scale[o] + shift[o];
    v = v >= 0.f ? v : NEG_SLOPE*v;
    tile[ty][tx] = v;
    __syncthreads();
    out[(size_t)b*256*NPTS + (size_t)(o0 + ty)*NPTS + n0 + tx] = tile[tx][ty];
}

// ---------------------------------------------------------------------------
// Host side
// ---------------------------------------------------------------------------
static void* sym(const void* s) { void* p = nullptr; cudaGetSymbolAddress(&p, s); return p; }

extern "C" void kernel_launch(void* const* d_in, const int* in_sizes, int n_in,
                              void* d_out, int out_size) {
    const float* x  = (const float*)d_in[0];
    const float* W[4] = { (const float*)d_in[1], (const float*)d_in[4],
                          (const float*)d_in[7], (const float*)d_in[10] };
    const float* G[4] = { (const float*)d_in[2], (const float*)d_in[5],
                          (const float*)d_in[8], (const float*)d_in[11] };
    const float* Bb[4] = { (const float*)d_in[3], (const float*)d_in[6],
                           (const float*)d_in[9], (const float*)d_in[12] };
    const float* W6 = (const float*)d_in[13];
    const float* g6 = (const float*)d_in[14];
    const float* b6 = (const float*)d_in[15];
    const float* W5 = (const float*)d_in[16];
    const float* g5 = (const float*)d_in[17];
    const float* b5 = (const float*)d_in[18];

    float*  f0   = (float*)sym(g_f0);
    float*  x1   = (float*)sym(g_x1);
    float*  x2   = (float*)sym(g_x2);
    float*  x3   = (float*)sym(g_x3);
    float*  x4   = (float*)sym(g_x4);
    float*  pd   = (float*)sym(g_pd);
    int*    idx  = (int*)  sym(g_idx);
    float*  wa   = (float*)sym(g_wa);
    float*  wd   = (float*)sym(g_wd);
    float*  Tb   = (float*)sym(g_T);
    float*  hmax = (float*)sym(g_hmax);
    float*  hmin = (float*)sym(g_hmin);
    float*  Pb   = (float*)sym(g_P);
    float*  cat  = (float*)sym(g_cat);
    float*  gmax = (float*)sym(g_gmax);
    double* s0   = (double*)sym(g_sum);
    double* s2   = (double*)sym(g_sum2);
    float*  sc   = (float*)sym(g_scale);
    float*  sh   = (float*)sym(g_shift);

    // input transpose (B,3,N) -> (B,N,3)
    transpose_in_kernel<<<(NB*3*NPTS + 255)/256, 256>>>(x, f0);

    const float* feats[4] = { f0, x1, x2, x3 };
    float*       outs [4] = { x1, x2, x3, x4 };
    const int    Cs[4] = { 3, 64, 64, 128 };
    const int    Os[4] = { 64, 64, 128, 256 };

    for (int L = 0; L < 4; L++) {
        int C = Cs[L], O = Os[L];
        const float* feat = feats[L];

        // weights split + center term (keeps dist at profiled launch slot #3)
        prep_w_kernel<<<(O*C + 255)/256, 256>>>(W[L], O, C, wa, wd);
        gemm_nt_kernel<<<dim3((BNTOT + 127)/128, O/64), 256>>>(feat, wd, Tb, BNTOT, O, C);

        // kNN: symmetric negative squared distance + top-20
        dim3 ggrid(NPAIRS, 1, NB);
        if (C == 3) dist_sym_kernel<4><<<ggrid, 256>>>(feat, pd, C);
        else        dist_sym_kernel<16><<<ggrid, 256>>>(feat, pd, C);
        topk_kernel<<<BNTOT, 128>>>(pd, idx);

        zero_stats_kernel<<<1, 256>>>(s0, s2);
        // fused gathered GEMM + k-reduction + BN stats (no H in HBM)
        fused_edge_kernel<<<dim3(BNTOT/FP, O/64), 256>>>(
            feat, wa, Tb, idx, C, O, hmax, hmin, s0, s2);
        bn_params_kernel<<<1, 256>>>(s0, s2, G[L], Bb[L], O, (double)MEDGE, sc, sh);
        edge_finalize_kernel<<<(BNTOT*O + 255)/256, 256>>>(hmax, hmin, sc, sh, outs[L], O);
    }

    // --- point conv h6 = lrelu(bn(x4 . W6^T)), then x5 = max over n ---
    gemm_nt_kernel<<<dim3(BNTOT/128, 256/64), 256>>>(x4, W6, Pb, BNTOT, 256, 256);
    zero_stats_kernel<<<1, 256>>>(s0, s2);
    colreduce_kernel<<<dim3(256/64, BNTOT/256), 256>>>(Pb, 256, s0, s2);
    bn_params_kernel<<<1, 256>>>(s0, s2, g6, b6, 256, (double)BNTOT, sc, sh);
    h6_finalize_kernel<<<dim3(256/64, NB), 256>>>(Pb, sc, sh, gmax);

    // --- concat [x1,x2,x3,x4,x5] -> 768 ---
    cat_kernel<<<(int)(((size_t)BNTOT*768 + 255)/256), 256>>>(x1, x2, x3, x4, gmax, cat);

    // --- final point conv + transpose output ---
    gemm_nt_kernel<<<dim3(BNTOT/128, 256/64), 256>>>(cat, W5, Pb, BNTOT, 256, 768);
    zero_stats_kernel<<<1, 256>>>(s0, s2);
    colreduce_kernel<<<dim3(256/64, BNTOT/256), 256>>>(Pb, 256, s0, s2);
    bn_params_kernel<<<1, 256>>>(s0, s2, g5, b5, 256, (double)BNTOT, sc, sh);
    out_transpose_kernel<<<dim3(NPTS/32, 256/32, NB), dim3(32, 32)>>>(Pb, sc, sh, (float*)d_out);
}

// round 7
// speedup vs baseline: 1.2197x; 1.1003x over previous
#include <cuda_runtime.h>
#include <cuda_bf16.h>
#include <math.h>

// ---------------------------------------------------------------------------
// Problem constants
// ---------------------------------------------------------------------------
#define NB 8
#define NPTS 2048
#define BNTOT (NB*NPTS)          // 16384
#define KNN 20
#define MEDGE (BNTOT*KNN)        // 327680
#define NEG_SLOPE 0.2f
#define BN_EPS 1e-5f
#define NT 16                    // 2048/128 tiles per dim
#define NPAIRS (NT*(NT+1)/2)     // 136

// ---------------------------------------------------------------------------
// Scratch (device globals -- no allocation allowed)
// ---------------------------------------------------------------------------
__device__ float g_f0  [BNTOT*3];
__device__ float g_x1  [BNTOT*64];
__device__ float g_x2  [BNTOT*64];
__device__ float g_x3  [BNTOT*128];
__device__ float g_x4  [BNTOT*256];
__device__ float g_pd  [(size_t)NB*NPTS*NPTS];       // 134 MB
__device__ int   g_idx [MEDGE];
__device__ float g_wa  [256*128];
__device__ float g_wd  [256*128];
__device__ float g_T   [BNTOT*256];
__device__ float g_hmax[BNTOT*256];
__device__ float g_hmin[BNTOT*256];
__device__ float g_P   [BNTOT*256];
__device__ float g_cat [BNTOT*768];
__device__ float g_gmax[NB*256];
__device__ double g_sum [256];
__device__ double g_sum2[256];
__device__ float g_scale[256];
__device__ float g_shift[256];

// ---------------------------------------------------------------------------
// Small elementwise kernels
// ---------------------------------------------------------------------------
__global__ void transpose_in_kernel(const float* __restrict__ x, float* __restrict__ f) {
    int i = blockIdx.x*256 + threadIdx.x;                 // B*3*N = 49152
    if (i >= NB*3*NPTS) return;
    int b = i / (3*NPTS);
    int rem = i - b*3*NPTS;
    int c = rem / NPTS;
    int n = rem - c*NPTS;
    f[(b*NPTS + n)*3 + c] = x[i];
}

__global__ void prep_w_kernel(const float* __restrict__ W, int O, int C,
                              float* __restrict__ wa, float* __restrict__ wd) {
    int i = blockIdx.x*256 + threadIdx.x;
    if (i >= O*C) return;
    int o = i / C, c = i - o*C;
    float a = W[o*2*C + c];
    wa[i] = a;
    wd[i] = W[o*2*C + C + c] - a;
}

__global__ void zero_stats_kernel(double* s, double* s2) {
    int t = threadIdx.x;
    if (t < 256) { s[t] = 0.0; s2[t] = 0.0; }
}

// ---------------------------------------------------------------------------
// SYMMETRIC squared-distance kernel: pd[b,i,j] = -sum_c (x_i[c]-x_j[c])^2
// Upper-triangular 128x128 tile pairs; off-diagonal tiles written twice.
// Bitwise identical to full computation.
// ---------------------------------------------------------------------------
template<int KS>
__global__ __launch_bounds__(256)
void dist_sym_kernel(const float* __restrict__ feat, float* __restrict__ pd, int C) {
    __shared__ float As[KS][132];
    __shared__ float Bs[KS][132];
    int b = blockIdx.z;
    int Lp = blockIdx.x;
    int ti = 0;
    while (Lp >= NT - ti) { Lp -= NT - ti; ti++; }
    int tj = ti + Lp;
    int m0 = ti*128, n0 = tj*128;
    bool diag = (ti == tj);

    const float* F = feat + (size_t)b*NPTS*C;
    int tid = threadIdx.x;
    int tx = tid & 15, ty = tid >> 4;

    float acc[8][8];
#pragma unroll
    for (int i = 0; i < 8; i++)
#pragma unroll
        for (int j = 0; j < 8; j++) acc[i][j] = 0.f;

    for (int k0 = 0; k0 < C; k0 += KS) {
#pragma unroll
        for (int e = tid; e < 128*KS; e += 256) {
            int c = e % KS, r = e / KS;
            float va = 0.f, vb = 0.f;
            if (k0 + c < C) {
                va = F[(size_t)(m0 + r)*C + k0 + c];
                vb = F[(size_t)(n0 + r)*C + k0 + c];
            }
            As[c][r] = va;
            Bs[c][r] = vb;
        }
        __syncthreads();
#pragma unroll
        for (int k = 0; k < KS; k++) {
            float af[8], bf[8];
#pragma unroll
            for (int i = 0; i < 8; i++) af[i] = As[k][ty*8 + i];
#pragma unroll
            for (int j = 0; j < 8; j++) bf[j] = Bs[k][tx*8 + j];
#pragma unroll
            for (int i = 0; i < 8; i++)
#pragma unroll
                for (int j = 0; j < 8; j++) {
                    float d = af[i] - bf[j];
                    acc[i][j] = fmaf(d, d, acc[i][j]);
                }
        }
        __syncthreads();
    }

    float* pdb = pd + (size_t)b*NPTS*NPTS;
#pragma unroll
    for (int i = 0; i < 8; i++) {
        int m = m0 + ty*8 + i;
        float4 w0 = make_float4(-acc[i][0], -acc[i][1], -acc[i][2], -acc[i][3]);
        float4 w1 = make_float4(-acc[i][4], -acc[i][5], -acc[i][6], -acc[i][7]);
        float4* dst = (float4*)&pdb[(size_t)m*NPTS + n0 + tx*8];
        dst[0] = w0;
        dst[1] = w1;
    }
    if (!diag) {
#pragma unroll
        for (int j = 0; j < 8; j++) {
            int n = n0 + tx*8 + j;
            float4 w0 = make_float4(-acc[0][j], -acc[1][j], -acc[2][j], -acc[3][j]);
            float4 w1 = make_float4(-acc[4][j], -acc[5][j], -acc[6][j], -acc[7][j]);
            float4* dst = (float4*)&pdb[(size_t)n*NPTS + m0 + ty*8];
            dst[0] = w0;
            dst[1] = w1;
        }
    }
}

// ---------------------------------------------------------------------------
// WARP-PER-ROW top-K: 1 warp owns a 2048-row, values live in 64 registers per
// lane. No block barriers. Selection order + tie rules identical to the old
// iterative argmax (value desc, global index asc) -> bitwise-identical idx.
// Lane l owns elements idx = m4*128 + l*4 + j  (m4=0..15, j=0..3).
// ---------------------------------------------------------------------------
__global__ __launch_bounds__(256)
void topk_warp_kernel(const float* __restrict__ pd, int* __restrict__ idx) {
    int w = threadIdx.x >> 5, l = threadIdx.x & 31;
    int bn = blockIdx.x*8 + w;
    const float* row = pd + (size_t)bn*NPTS;

    float vals[64];
#pragma unroll
    for (int m = 0; m < 16; m++) {
        float4 v = *(const float4*)(row + m*128 + l*4);
        vals[m*4+0] = v.x; vals[m*4+1] = v.y; vals[m*4+2] = v.z; vals[m*4+3] = v.w;
    }

    unsigned long long excl = 0ull;
    // per-lane cached group maxima (4 groups of 16 slots; slot order == idx order)
    float gv[4]; int gm[4];
#pragma unroll
    for (int g = 0; g < 4; g++) {
        float bv = -INFINITY; int bm = g*16;
#pragma unroll
        for (int m = g*16; m < (g+1)*16; m++)
            if (vals[m] > bv) { bv = vals[m]; bm = m; }   // strict > keeps lowest slot
        gv[g] = bv; gm[g] = bm;
    }

    int my_out = 0;
    for (int it = 0; it < KNN; it++) {
        // local best across groups (strict > keeps earlier group = lower idx)
        float bv = gv[0]; int bm = gm[0];
#pragma unroll
        for (int g = 1; g < 4; g++)
            if (gv[g] > bv) { bv = gv[g]; bm = gm[g]; }
        int gidx = ((bm >> 2) << 7) + (l << 2) + (bm & 3);   // global column index

        float v = bv; int ix = gidx;
#pragma unroll
        for (int s = 16; s > 0; s >>= 1) {
            float ov = __shfl_xor_sync(0xffffffff, v, s);
            int   oi = __shfl_xor_sync(0xffffffff, ix, s);
            if (ov > v || (ov == v && oi < ix)) { v = ov; ix = oi; }
        }
        // ix = winner global index this iteration (broadcast to all lanes)
        if (l == it) my_out = ix;

        int owner = (ix >> 2) & 31;
        if (l == owner) {
            int sl = ((ix >> 7) << 2) | (ix & 3);    // local slot
            excl |= 1ull << sl;
            int g = sl >> 4;
            float bv2 = -INFINITY; int bm2 = g*16;
#pragma unroll
            for (int m = 0; m < 16; m++) {
                int mm = 0;
                switch (g) { case 0: mm = m; break; case 1: mm = 16+m; break;
                             case 2: mm = 32+m; break; default: mm = 48+m; }
                if (!((excl >> mm) & 1ull) && vals[mm] > bv2) { bv2 = vals[mm]; bm2 = mm; }
            }
            gv[g] = bv2; gm[g] = bm2;
        }
    }
    if (l < KNN) idx[bn*KNN + l] = my_out;
}

// ---------------------------------------------------------------------------
// Generic NT GEMM (used for T and the point convs):
// C[m,n] = sum_k A[m,k]*B[n,k]
// ---------------------------------------------------------------------------
__global__ __launch_bounds__(256)
void gemm_nt_kernel(const float* __restrict__ A, const float* __restrict__ B,
                    float* __restrict__ C, int M, int N, int K) {
    __shared__ float As[16][129];
    __shared__ float Bs[16][65];
    int tid = threadIdx.x;
    int tx = tid & 15;
    int ty = tid >> 4;
    int m0 = blockIdx.x * 128;
    int n0 = blockIdx.y * 64;

    float acc[8][4];
#pragma unroll
    for (int i = 0; i < 8; i++)
#pragma unroll
        for (int j = 0; j < 4; j++) acc[i][j] = 0.f;

    for (int k0 = 0; k0 < K; k0 += 16) {
#pragma unroll
        for (int i = 0; i < 8; i++) {
            int e = tid + i*256;
            int c = e & 15, r = e >> 4;
            int m = m0 + r;
            float v = 0.f;
            if (m < M && k0 + c < K) v = A[(size_t)m*K + k0 + c];
            As[c][r] = v;
        }
#pragma unroll
        for (int i = 0; i < 4; i++) {
            int e = tid + i*256;
            int c = e & 15, r = e >> 4;
            float v = 0.f;
            if (k0 + c < K) v = B[(size_t)(n0 + r)*K + k0 + c];
            Bs[c][r] = v;
        }
        __syncthreads();
#pragma unroll
        for (int k = 0; k < 16; k++) {
            float af[8], bf[4];
#pragma unroll
            for (int i = 0; i < 8; i++) af[i] = As[k][ty*8 + i];
#pragma unroll
            for (int j = 0; j < 4; j++) bf[j] = Bs[k][tx*4 + j];
#pragma unroll
            for (int i = 0; i < 8; i++)
#pragma unroll
                for (int j = 0; j < 4; j++) acc[i][j] += af[i]*bf[j];
        }
        __syncthreads();
    }

#pragma unroll
    for (int i = 0; i < 8; i++) {
        int m = m0 + ty*8 + i;
        if (m >= M) continue;
#pragma unroll
        for (int j = 0; j < 4; j++) {
            int n = n0 + tx*4 + j;
            C[(size_t)m*N + n] = acc[i][j];
        }
    }
}

// ---------------------------------------------------------------------------
// FUSED edge-conv: per block, 8 points x 20 neighbors (160 rows) x 64 channels.
// H = gather(feat)[row] . wa + T[point]; reduces over k in-block.
// ---------------------------------------------------------------------------
#define FP    8
#define FROWS (FP*KNN)            // 160
#define AS_STRIDE 161             // 161 % 32 == 1  -> conflict-free
#define BS_BASE   (16*AS_STRIDE)  // 2576 floats (16B aligned)
#define BS_STRIDE 68              // rows 16B aligned
#define STG_STRIDE 66

__global__ __launch_bounds__(256)
void fused_edge_kernel(const float* __restrict__ feat,   // [BNTOT, C]
                       const float* __restrict__ wa,     // [O, C]
                       const float* __restrict__ T,      // [BNTOT, O]
                       const int* __restrict__ idx,      // [BNTOT, KNN]
                       int C, int O,
                       float* __restrict__ hmax, float* __restrict__ hmin,
                       double* __restrict__ gsum, double* __restrict__ gsum2) {
    __shared__ float pool[FROWS*STG_STRIDE];   // 10560 floats
    __shared__ int   sidx[FROWS];
    __shared__ float sT[FP*64];

    int tid = threadIdx.x;
    int p0  = blockIdx.x * FP;
    int n0  = blockIdx.y * 64;

    if (tid < FROWS) {
        int p  = tid / KNN;
        int k  = tid - p*KNN;
        int bn = p0 + p;
        sidx[tid] = (bn >> 11)*NPTS + idx[bn*KNN + k];
    }
    {
        int e = tid;
        sT[e] = T[(size_t)(p0 + (e >> 6))*O + n0 + (e & 63)];
        e += 256;
        sT[e] = T[(size_t)(p0 + (e >> 6))*O + n0 + (e & 63)];
    }
    __syncthreads();

    int tx = tid & 7;
    int ty = tid >> 3;

    float acc[5][8];
#pragma unroll
    for (int i = 0; i < 5; i++)
#pragma unroll
        for (int j = 0; j < 8; j++) acc[i][j] = 0.f;

    for (int k0 = 0; k0 < C; k0 += 16) {
#pragma unroll
        for (int i = 0; i < 10; i++) {
            int e = tid + i*256;
            int c = e & 15, r = e >> 4;
            float v = 0.f;
            if (k0 + c < C) v = feat[(size_t)sidx[r]*C + k0 + c];
            pool[c*AS_STRIDE + r] = v;
        }
#pragma unroll
        for (int i = 0; i < 4; i++) {
            int e = tid + i*256;
            int c = e & 15, r = e >> 4;
            float v = 0.f;
            if (k0 + c < C) v = wa[(size_t)(n0 + r)*C + k0 + c];
            pool[BS_BASE + c*BS_STRIDE + r] = v;
        }
        __syncthreads();
#pragma unroll
        for (int k = 0; k < 16; k++) {
            float af[5];
#pragma unroll
            for (int i = 0; i < 5; i++) af[i] = pool[k*AS_STRIDE + ty*5 + i];
            const float4* bp = (const float4*)&pool[BS_BASE + k*BS_STRIDE + tx*8];
            float4 b0 = bp[0], b1 = bp[1];
            float bf[8] = { b0.x, b0.y, b0.z, b0.w, b1.x, b1.y, b1.z, b1.w };
#pragma unroll
            for (int i = 0; i < 5; i++)
#pragma unroll
                for (int j = 0; j < 8; j++) acc[i][j] += af[i]*bf[j];
        }
        __syncthreads();
    }

#pragma unroll
    for (int i = 0; i < 5; i++) {
        int r = ty*5 + i;
        int p = r / KNN;
#pragma unroll
        for (int j = 0; j < 8; j++) {
            float v = acc[i][j] + sT[p*64 + tx*8 + j];
            pool[r*STG_STRIDE + tx*8 + j] = v;
        }
    }
    __syncthreads();

    int ol = tid & 63;
    int gi = tid >> 6;
    float s = 0.f, s2 = 0.f;
#pragma unroll
    for (int half = 0; half < 2; half++) {
        int p = gi + half*4;
        float mx = -INFINITY, mn = INFINITY;
#pragma unroll
        for (int k = 0; k < KNN; k++) {
            float v = pool[(p*KNN + k)*STG_STRIDE + ol];
            mx = fmaxf(mx, v); mn = fminf(mn, v);
            s += v; s2 += v*v;
        }
        size_t oi = (size_t)(p0 + p)*O + n0 + ol;
        hmax[oi] = mx;
        hmin[oi] = mn;
    }
    __syncthreads();
    sT[gi*64 + ol] = s;
    sT[256 + gi*64 + ol] = s2;
    __syncthreads();
    if (gi == 0) {
        float ts  = sT[ol] + sT[64+ol] + sT[128+ol] + sT[192+ol];
        float ts2 = sT[256+ol] + sT[320+ol] + sT[384+ol] + sT[448+ol];
        atomicAdd(&gsum[n0 + ol],  (double)ts);
        atomicAdd(&gsum2[n0 + ol], (double)ts2);
    }
}

// ---------------------------------------------------------------------------
// Column reduce for point convs (sum/sumsq per channel)
// ---------------------------------------------------------------------------
__global__ __launch_bounds__(256)
void colreduce_kernel(const float* __restrict__ P, int O,
                      double* __restrict__ gsum, double* __restrict__ gsum2) {
    int ol = threadIdx.x & 63;
    int gi = threadIdx.x >> 6;
    int o  = blockIdx.x*64 + ol;
    int r0 = blockIdx.y*256 + gi*64;
    float s = 0.f, s2 = 0.f;
    for (int r = r0; r < r0 + 64; r++) {
        float v = P[(size_t)r*O + o];
        s += v; s2 += v*v;
    }
    __shared__ float ss[4][64], ssq[4][64];
    ss[gi][ol] = s; ssq[gi][ol] = s2;
    __syncthreads();
    if (gi == 0) {
        atomicAdd(&gsum[o],  (double)(ss[0][ol]+ss[1][ol]+ss[2][ol]+ss[3][ol]));
        atomicAdd(&gsum2[o], (double)(ssq[0][ol]+ssq[1][ol]+ssq[2][ol]+ssq[3][ol]));
    }
}

__global__ void bn_params_kernel(const double* __restrict__ gsum, const double* __restrict__ gsum2,
                                 const float* __restrict__ g, const float* __restrict__ b,
                                 int O, double cnt,
                                 float* __restrict__ scale, float* __restrict__ shift) {
    int o = threadIdx.x;
    if (o >= O) return;
    double m   = gsum[o] / cnt;
    double var = gsum2[o] / cnt - m*m;
    float sc = g[o] * rsqrtf((float)var + BN_EPS);
    scale[o] = sc;
    shift[o] = b[o] - (float)m * sc;
}

__global__ void edge_finalize_kernel(const float* __restrict__ hmax, const float* __restrict__ hmin,
                                     const float* __restrict__ scale, const float* __restrict__ shift,
                                     float* __restrict__ out, int O) {
    int i = blockIdx.x*256 + threadIdx.x;
    if (i >= BNTOT*O) return;
    int o = i & (O - 1);
    float sc = scale[o];
    float v = (sc >= 0.f ? hmax[i] : hmin[i]) * sc + shift[o];
    out[i] = v >= 0.f ? v : NEG_SLOPE*v;
}

// h6: act + global max over n per (b,o)
__global__ __launch_bounds__(256)
void h6_finalize_kernel(const float* __restrict__ P,
                        const float* __restrict__ scale, const float* __restrict__ shift,
                        float* __restrict__ gmax) {
    int ol = threadIdx.x & 63;
    int gi = threadIdx.x >> 6;
    int o = blockIdx.x*64 + ol;
    int b = blockIdx.y;
    float sc = scale[o], sh = shift[o];
    float mx = -INFINITY;
    for (int n = gi*512; n < (gi+1)*512; n++) {
        float v = P[((size_t)(b*NPTS + n))*256 + o]*sc + sh;
        v = v >= 0.f ? v : NEG_SLOPE*v;
        mx = fmaxf(mx, v);
    }
    __shared__ float sm[4][64];
    sm[gi][ol] = mx;
    __syncthreads();
    if (gi == 0)
        gmax[b*256 + o] = fmaxf(fmaxf(sm[0][ol], sm[1][ol]), fmaxf(sm[2][ol], sm[3][ol]));
}

__global__ void cat_kernel(const float* __restrict__ x1, const float* __restrict__ x2,
                           const float* __restrict__ x3, const float* __restrict__ x4,
                           const float* __restrict__ gmax, float* __restrict__ cat) {
    size_t i = (size_t)blockIdx.x*256 + threadIdx.x;
    if (i >= (size_t)BNTOT*768) return;
    int bn = (int)(i / 768);
    int c  = (int)(i - (size_t)bn*768);
    float v;
    if      (c < 64)  v = x1[bn*64  + c];
    else if (c < 128) v = x2[bn*64  + c - 64];
    else if (c < 256) v = x3[bn*128 + c - 128];
    else if (c < 512) v = x4[bn*256 + c - 256];
    else              v = gmax[(bn >> 11)*256 + c - 512];
    cat[i] = v;
}

// final: act + transpose (B,N,256) -> (B,256,N)
__global__ void out_transpose_kernel(const float* __restrict__ P,
                                     const float* __restrict__ scale, const float* __restrict__ shift,
                                     float* __restrict__ out) {
    __shared__ float tile[32][33];
    int b  = blockIdx.z;
    int n0 = blockIdx.x*32, o0 = blockIdx.y*32;
    int tx = threadIdx.x, ty = threadIdx.y;
    int o = o0 + tx;
    float v = P[((size_t)(b*NPTS + n0 + ty))*256 + o]*scale[o] + shift[o];
    v = v >= 0.f ? v : NEG_SLOPE*v;
    tile[ty][tx] = v;
    __syncthreads();
    out[(size_t)b*256*NPTS + (size_t)(o0 + ty)*NPTS + n0 + tx] = tile[tx][ty];
}

// ---------------------------------------------------------------------------
// Host side
// ---------------------------------------------------------------------------
static void* sym(const void* s) { void* p = nullptr; cudaGetSymbolAddress(&p, s); return p; }

extern "C" void kernel_launch(void* const* d_in, const int* in_sizes, int n_in,
                              void* d_out, int out_size) {
    const float* x  = (const float*)d_in[0];
    const float* W[4] = { (const float*)d_in[1], (const float*)d_in[4],
                          (const float*)d_in[7], (const float*)d_in[10] };
    const float* G[4] = { (const float*)d_in[2], (const float*)d_in[5],
                          (const float*)d_in[8], (const float*)d_in[11] };
    const float* Bb[4] = { (const float*)d_in[3], (const float*)d_in[6],
                           (const float*)d_in[9], (const float*)d_in[12] };
    const float* W6 = (const float*)d_in[13];
    const float* g6 = (const float*)d_in[14];
    const float* b6 = (const float*)d_in[15];
    const float* W5 = (const float*)d_in[16];
    const float* g5 = (const float*)d_in[17];
    const float* b5 = (const float*)d_in[18];

    float*  f0   = (float*)sym(g_f0);
    float*  x1   = (float*)sym(g_x1);
    float*  x2   = (float*)sym(g_x2);
    float*  x3   = (float*)sym(g_x3);
    float*  x4   = (float*)sym(g_x4);
    float*  pd   = (float*)sym(g_pd);
    int*    idx  = (int*)  sym(g_idx);
    float*  wa   = (float*)sym(g_wa);
    float*  wd   = (float*)sym(g_wd);
    float*  Tb   = (float*)sym(g_T);
    float*  hmax = (float*)sym(g_hmax);
    float*  hmin = (float*)sym(g_hmin);
    float*  Pb   = (float*)sym(g_P);
    float*  cat  = (float*)sym(g_cat);
    float*  gmax = (float*)sym(g_gmax);
    double* s0   = (double*)sym(g_sum);
    double* s2   = (double*)sym(g_sum2);
    float*  sc   = (float*)sym(g_scale);
    float*  sh   = (float*)sym(g_shift);

    // input transpose (B,3,N) -> (B,N,3)
    transpose_in_kernel<<<(NB*3*NPTS + 255)/256, 256>>>(x, f0);

    const float* feats[4] = { f0, x1, x2, x3 };
    float*       outs [4] = { x1, x2, x3, x4 };
    const int    Cs[4] = { 3, 64, 64, 128 };
    const int    Os[4] = { 64, 64, 128, 256 };

    for (int L = 0; L < 4; L++) {
        int C = Cs[L], O = Os[L];
        const float* feat = feats[L];

        prep_w_kernel<<<(O*C + 255)/256, 256>>>(W[L], O, C, wa, wd);
        gemm_nt_kernel<<<dim3((BNTOT + 127)/128, O/64), 256>>>(feat, wd, Tb, BNTOT, O, C);

        // kNN: symmetric negative squared distance + warp-per-row top-20
        dim3 ggrid(NPAIRS, 1, NB);
        if (C == 3) dist_sym_kernel<4><<<ggrid, 256>>>(feat, pd, C);
        else        dist_sym_kernel<16><<<ggrid, 256>>>(feat, pd, C);
        topk_warp_kernel<<<BNTOT/8, 256>>>(pd, idx);

        zero_stats_kernel<<<1, 256>>>(s0, s2);
        fused_edge_kernel<<<dim3(BNTOT/FP, O/64), 256>>>(
            feat, wa, Tb, idx, C, O, hmax, hmin, s0, s2);
        bn_params_kernel<<<1, 256>>>(s0, s2, G[L], Bb[L], O, (double)MEDGE, sc, sh);
        edge_finalize_kernel<<<(BNTOT*O + 255)/256, 256>>>(hmax, hmin, sc, sh, outs[L], O);
    }

    // --- point conv h6 = lrelu(bn(x4 . W6^T)), then x5 = max over n ---
    gemm_nt_kernel<<<dim3(BNTOT/128, 256/64), 256>>>(x4, W6, Pb, BNTOT, 256, 256);
    zero_stats_kernel<<<1, 256>>>(s0, s2);
    colreduce_kernel<<<dim3(256/64, BNTOT/256), 256>>>(Pb, 256, s0, s2);
    bn_params_kernel<<<1, 256>>>(s0, s2, g6, b6, 256, (double)BNTOT, sc, sh);
    h6_finalize_kernel<<<dim3(256/64, NB), 256>>>(Pb, sc, sh, gmax);

    // --- concat [x1,x2,x3,x4,x5] -> 768 ---
    cat_kernel<<<(int)(((size_t)BNTOT*768 + 255)/256), 256>>>(x1, x2, x3, x4, gmax, cat);

    // --- final point conv + transpose output ---
    gemm_nt_kernel<<<dim3(BNTOT/128, 256/64), 256>>>(cat, W5, Pb, BNTOT, 256, 768);
    zero_stats_kernel<<<1, 256>>>(s0, s2);
    colreduce_kernel<<<dim3(256/64, BNTOT/256), 256>>>(Pb, 256, s0, s2);
    bn_params_kernel<<<1, 256>>>(s0, s2, g5, b5, 256, (double)BNTOT, sc, sh);
    out_transpose_kernel<<<dim3(NPTS/32, 256/32, NB), dim3(32, 32)>>>(Pb, sc, sh, (float*)d_out);
}

// round 9
// speedup vs baseline: 1.3554x; 1.1113x over previous
#include <cuda_runtime.h>
#include <cuda_bf16.h>
#include <math.h>

// ---------------------------------------------------------------------------
// Problem constants
// ---------------------------------------------------------------------------
#define NB 8
#define NPTS 2048
#define BNTOT (NB*NPTS)          // 16384
#define KNN 20
#define MEDGE (BNTOT*KNN)        // 327680
#define NEG_SLOPE 0.2f
#define BN_EPS 1e-5f
#define NT 16                    // 2048/128 tiles per dim
#define NPAIRS (NT*(NT+1)/2)     // 136

// ---------------------------------------------------------------------------
// Packed fp32x2 helpers (Blackwell): one instr = two fp32 ops, same rounding
// as the scalar ops -> bitwise-identical results at 2x fma-pipe throughput.
// Packed pair carried as unsigned long long (b64 register class, "l").
// ---------------------------------------------------------------------------
typedef unsigned long long u64;

__device__ __forceinline__ u64 f2_pack(float lo, float hi) {
    u64 d;
    asm("mov.b64 %0, {%1, %2};" : "=l"(d)
        : "r"(__float_as_uint(lo)), "r"(__float_as_uint(hi)));
    return d;
}
__device__ __forceinline__ float2 f2_unpack(u64 d) {
    unsigned lo, hi;
    asm("mov.b64 {%0, %1}, %2;" : "=r"(lo), "=r"(hi) : "l"(d));
    return make_float2(__uint_as_float(lo), __uint_as_float(hi));
}
__device__ __forceinline__ u64 f2_fma(u64 a, u64 b, u64 c) {
    u64 d;
    asm("fma.rn.f32x2 %0, %1, %2, %3;" : "=l"(d) : "l"(a), "l"(b), "l"(c));
    return d;
}
__device__ __forceinline__ u64 f2_add(u64 a, u64 b) {
    u64 d;
    asm("add.rn.f32x2 %0, %1, %2;" : "=l"(d) : "l"(a), "l"(b));
    return d;
}

// ---------------------------------------------------------------------------
// Scratch (device globals -- no allocation allowed)
// ---------------------------------------------------------------------------
__device__ float g_f0  [BNTOT*3];
__device__ float g_x1  [BNTOT*64];
__device__ float g_x2  [BNTOT*64];
__device__ float g_x3  [BNTOT*128];
__device__ float g_x4  [BNTOT*256];
__device__ float g_pd  [(size_t)NB*NPTS*NPTS];       // 134 MB
__device__ int   g_idx [MEDGE];
__device__ float g_wa  [256*128];
__device__ float g_wd  [256*128];
__device__ float g_T   [BNTOT*256];
__device__ float g_hmax[BNTOT*256];
__device__ float g_hmin[BNTOT*256];
__device__ float g_P   [BNTOT*256];
__device__ float g_cat [BNTOT*768];
__device__ float g_gmax[NB*256];
__device__ double g_sum [256];
__device__ double g_sum2[256];
__device__ float g_scale[256];
__device__ float g_shift[256];

// ---------------------------------------------------------------------------
// Small elementwise kernels
// ---------------------------------------------------------------------------
__global__ void transpose_in_kernel(const float* __restrict__ x, float* __restrict__ f) {
    int i = blockIdx.x*256 + threadIdx.x;                 // B*3*N = 49152
    if (i >= NB*3*NPTS) return;
    int b = i / (3*NPTS);
    int rem = i - b*3*NPTS;
    int c = rem / NPTS;
    int n = rem - c*NPTS;
    f[(b*NPTS + n)*3 + c] = x[i];
}

__global__ void prep_w_kernel(const float* __restrict__ W, int O, int C,
                              float* __restrict__ wa, float* __restrict__ wd) {
    int i = blockIdx.x*256 + threadIdx.x;
    if (i >= O*C) return;
    int o = i / C, c = i - o*C;
    float a = W[o*2*C + c];
    wa[i] = a;
    wd[i] = W[o*2*C + C + c] - a;
}

__global__ void zero_stats_kernel(double* s, double* s2) {
    int t = threadIdx.x;
    if (t < 256) { s[t] = 0.0; s2[t] = 0.0; }
}

// ---------------------------------------------------------------------------
// SYMMETRIC squared-distance kernel: pd[b,i,j] = -sum_c (x_i[c]-x_j[c])^2
// Upper-triangular 128x128 tile pairs; off-diagonal tiles written twice.
// Bs stored negated so d = a + (-b) (bitwise == a-b); inner loop in f32x2.
// Bitwise identical to the scalar full computation.
// ---------------------------------------------------------------------------
template<int KS>
__global__ __launch_bounds__(256)
void dist_sym_kernel(const float* __restrict__ feat, float* __restrict__ pd, int C) {
    __shared__ __align__(16) float As[KS][132];   // 132*4 % 16 == 0
    __shared__ __align__(16) float Bs[KS][132];
    int b = blockIdx.z;
    int Lp = blockIdx.x;
    int ti = 0;
    while (Lp >= NT - ti) { Lp -= NT - ti; ti++; }
    int tj = ti + Lp;
    int m0 = ti*128, n0 = tj*128;
    bool diag = (ti == tj);

    const float* F = feat + (size_t)b*NPTS*C;
    int tid = threadIdx.x;
    int tx = tid & 15, ty = tid >> 4;

    u64 acc2[8][4];
#pragma unroll
    for (int i = 0; i < 8; i++)
#pragma unroll
        for (int j = 0; j < 4; j++) acc2[i][j] = 0ull;   // (0.f, 0.f)

    for (int k0 = 0; k0 < C; k0 += KS) {
#pragma unroll
        for (int e = tid; e < 128*KS; e += 256) {
            int c = e % KS, r = e / KS;
            float va = 0.f, vb = 0.f;
            if (k0 + c < C) {
                va = F[(size_t)(m0 + r)*C + k0 + c];
                vb = F[(size_t)(n0 + r)*C + k0 + c];
            }
            As[c][r] = va;
            Bs[c][r] = -vb;          // negate so inner loop uses add.f32x2
        }
        __syncthreads();
#pragma unroll
        for (int k = 0; k < KS; k++) {
            float af[8];
#pragma unroll
            for (int i = 0; i < 8; i++) af[i] = As[k][ty*8 + i];
            const u64* bp = (const u64*)&Bs[k][tx*8];
            u64 b2[4] = { bp[0], bp[1], bp[2], bp[3] };
#pragma unroll
            for (int i = 0; i < 8; i++) {
                u64 a2 = f2_pack(af[i], af[i]);
#pragma unroll
                for (int jp = 0; jp < 4; jp++) {
                    u64 d2 = f2_add(a2, b2[jp]);       // (a-b0, a-b1)
                    acc2[i][jp] = f2_fma(d2, d2, acc2[i][jp]);
                }
            }
        }
        __syncthreads();
    }

    // unpack to negated distances
    float neg[8][8];
#pragma unroll
    for (int i = 0; i < 8; i++)
#pragma unroll
        for (int jp = 0; jp < 4; jp++) {
            float2 v = f2_unpack(acc2[i][jp]);
            neg[i][2*jp]   = -v.x;
            neg[i][2*jp+1] = -v.y;
        }

    float* pdb = pd + (size_t)b*NPTS*NPTS;
#pragma unroll
    for (int i = 0; i < 8; i++) {
        int m = m0 + ty*8 + i;
        float4 w0 = make_float4(neg[i][0], neg[i][1], neg[i][2], neg[i][3]);
        float4 w1 = make_float4(neg[i][4], neg[i][5], neg[i][6], neg[i][7]);
        float4* dst = (float4*)&pdb[(size_t)m*NPTS + n0 + tx*8];
        dst[0] = w0;
        dst[1] = w1;
    }
    if (!diag) {
#pragma unroll
        for (int j = 0; j < 8; j++) {
            int n = n0 + tx*8 + j;
            float4 w0 = make_float4(neg[0][j], neg[1][j], neg[2][j], neg[3][j]);
            float4 w1 = make_float4(neg[4][j], neg[5][j], neg[6][j], neg[7][j]);
            float4* dst = (float4*)&pdb[(size_t)n*NPTS + m0 + ty*8];
            dst[0] = w0;
            dst[1] = w1;
        }
    }
}

// ---------------------------------------------------------------------------
// WARP-PER-ROW top-K (selection order == jax top_k)
// ---------------------------------------------------------------------------
__global__ __launch_bounds__(256)
void topk_warp_kernel(const float* __restrict__ pd, int* __restrict__ idx) {
    int w = threadIdx.x >> 5, l = threadIdx.x & 31;
    int bn = blockIdx.x*8 + w;
    const float* row = pd + (size_t)bn*NPTS;

    float vals[64];
#pragma unroll
    for (int m = 0; m < 16; m++) {
        float4 v = *(const float4*)(row + m*128 + l*4);
        vals[m*4+0] = v.x; vals[m*4+1] = v.y; vals[m*4+2] = v.z; vals[m*4+3] = v.w;
    }

    unsigned long long excl = 0ull;
    float gv[4]; int gm[4];
#pragma unroll
    for (int g = 0; g < 4; g++) {
        float bv = -INFINITY; int bm = g*16;
#pragma unroll
        for (int m = g*16; m < (g+1)*16; m++)
            if (vals[m] > bv) { bv = vals[m]; bm = m; }
        gv[g] = bv; gm[g] = bm;
    }

    int my_out = 0;
    for (int it = 0; it < KNN; it++) {
        float bv = gv[0]; int bm = gm[0];
#pragma unroll
        for (int g = 1; g < 4; g++)
            if (gv[g] > bv) { bv = gv[g]; bm = gm[g]; }
        int gidx = ((bm >> 2) << 7) + (l << 2) + (bm & 3);

        float v = bv; int ix = gidx;
#pragma unroll
        for (int s = 16; s > 0; s >>= 1) {
            float ov = __shfl_xor_sync(0xffffffff, v, s);
            int   oi = __shfl_xor_sync(0xffffffff, ix, s);
            if (ov > v || (ov == v && oi < ix)) { v = ov; ix = oi; }
        }
        if (l == it) my_out = ix;

        int owner = (ix >> 2) & 31;
        if (l == owner) {
            int sl = ((ix >> 7) << 2) | (ix & 3);
            excl |= 1ull << sl;
            int g = sl >> 4;
            float bv2 = -INFINITY; int bm2 = g*16;
#pragma unroll
            for (int m = 0; m < 16; m++) {
                int mm = 0;
                switch (g) { case 0: mm = m; break; case 1: mm = 16+m; break;
                             case 2: mm = 32+m; break; default: mm = 48+m; }
                if (!((excl >> mm) & 1ull) && vals[mm] > bv2) { bv2 = vals[mm]; bm2 = mm; }
            }
            gv[g] = bv2; gm[g] = bm2;
        }
    }
    if (l < KNN) idx[bn*KNN + l] = my_out;
}

// ---------------------------------------------------------------------------
// Generic NT GEMM (T + point convs): C[m,n] = sum_k A[m,k]*B[n,k], f32x2 inner
// ---------------------------------------------------------------------------
__global__ __launch_bounds__(256)
void gemm_nt_kernel(const float* __restrict__ A, const float* __restrict__ B,
                    float* __restrict__ C, int M, int N, int K) {
    __shared__ __align__(16) float As[16][129];
    __shared__ __align__(16) float Bs[16][66];    // 66*4 % 8 == 0 for u64 loads
    int tid = threadIdx.x;
    int tx = tid & 15;
    int ty = tid >> 4;
    int m0 = blockIdx.x * 128;
    int n0 = blockIdx.y * 64;

    u64 acc2[8][2];
#pragma unroll
    for (int i = 0; i < 8; i++) { acc2[i][0] = 0ull; acc2[i][1] = 0ull; }

    for (int k0 = 0; k0 < K; k0 += 16) {
#pragma unroll
        for (int i = 0; i < 8; i++) {
            int e = tid + i*256;
            int c = e & 15, r = e >> 4;
            int m = m0 + r;
            float v = 0.f;
            if (m < M && k0 + c < K) v = A[(size_t)m*K + k0 + c];
            As[c][r] = v;
        }
#pragma unroll
        for (int i = 0; i < 4; i++) {
            int e = tid + i*256;
            int c = e & 15, r = e >> 4;
            float v = 0.f;
            if (k0 + c < K) v = B[(size_t)(n0 + r)*K + k0 + c];
            Bs[c][r] = v;
        }
        __syncthreads();
#pragma unroll
        for (int k = 0; k < 16; k++) {
            const u64* bp = (const u64*)&Bs[k][tx*4];
            u64 b0 = bp[0], b1 = bp[1];
#pragma unroll
            for (int i = 0; i < 8; i++) {
                float a = As[k][ty*8 + i];
                u64 a2 = f2_pack(a, a);
                acc2[i][0] = f2_fma(a2, b0, acc2[i][0]);
                acc2[i][1] = f2_fma(a2, b1, acc2[i][1]);
            }
        }
        __syncthreads();
    }

#pragma unroll
    for (int i = 0; i < 8; i++) {
        int m = m0 + ty*8 + i;
        if (m >= M) continue;
        float2 v0 = f2_unpack(acc2[i][0]);
        float2 v1 = f2_unpack(acc2[i][1]);
        float* dst = &C[(size_t)m*N + n0 + tx*4];
        dst[0] = v0.x; dst[1] = v0.y; dst[2] = v1.x; dst[3] = v1.y;
    }
}

// ---------------------------------------------------------------------------
// FUSED edge-conv: 8 points x 20 neighbors (160 rows) x 64 channels, f32x2.
// H = gather(feat)[row] . wa + T[point]; reduces over k in-block.
// ---------------------------------------------------------------------------
#define FP    8
#define FROWS (FP*KNN)            // 160
#define AS_STRIDE 161             // 161 % 32 == 1  -> conflict-free
#define BS_BASE   (16*AS_STRIDE)  // 2576 floats (16B aligned)
#define BS_STRIDE 68              // rows 16B aligned
#define STG_STRIDE 66

__global__ __launch_bounds__(256)
void fused_edge_kernel(const float* __restrict__ feat,   // [BNTOT, C]
                       const float* __restrict__ wa,     // [O, C]
                       const float* __restrict__ T,      // [BNTOT, O]
                       const int* __restrict__ idx,      // [BNTOT, KNN]
                       int C, int O,
                       float* __restrict__ hmax, float* __restrict__ hmin,
                       double* __restrict__ gsum, double* __restrict__ gsum2) {
    __shared__ __align__(16) float pool[FROWS*STG_STRIDE];   // 10560 floats
    __shared__ int   sidx[FROWS];
    __shared__ float sT[FP*64];

    int tid = threadIdx.x;
    int p0  = blockIdx.x * FP;
    int n0  = blockIdx.y * 64;

    if (tid < FROWS) {
        int p  = tid / KNN;
        int k  = tid - p*KNN;
        int bn = p0 + p;
        sidx[tid] = (bn >> 11)*NPTS + idx[bn*KNN + k];
    }
    {
        int e = tid;
        sT[e] = T[(size_t)(p0 + (e >> 6))*O + n0 + (e & 63)];
        e += 256;
        sT[e] = T[(size_t)(p0 + (e >> 6))*O + n0 + (e & 63)];
    }
    __syncthreads();

    int tx = tid & 7;
    int ty = tid >> 3;

    u64 acc2[5][4];
#pragma unroll
    for (int i = 0; i < 5; i++)
#pragma unroll
        for (int j = 0; j < 4; j++) acc2[i][j] = 0ull;

    for (int k0 = 0; k0 < C; k0 += 16) {
#pragma unroll
        for (int i = 0; i < 10; i++) {
            int e = tid + i*256;
            int c = e & 15, r = e >> 4;
            float v = 0.f;
            if (k0 + c < C) v = feat[(size_t)sidx[r]*C + k0 + c];
            pool[c*AS_STRIDE + r] = v;
        }
#pragma unroll
        for (int i = 0; i < 4; i++) {
            int e = tid + i*256;
            int c = e & 15, r = e >> 4;
            float v = 0.f;
            if (k0 + c < C) v = wa[(size_t)(n0 + r)*C + k0 + c];
            pool[BS_BASE + c*BS_STRIDE + r] = v;
        }
        __syncthreads();
#pragma unroll
        for (int k = 0; k < 16; k++) {
            const u64* bp = (const u64*)&pool[BS_BASE + k*BS_STRIDE + tx*8];
            u64 b2[4] = { bp[0], bp[1], bp[2], bp[3] };
#pragma unroll
            for (int i = 0; i < 5; i++) {
                float a = pool[k*AS_STRIDE + ty*5 + i];
                u64 a2 = f2_pack(a, a);
#pragma unroll
                for (int jp = 0; jp < 4; jp++)
                    acc2[i][jp] = f2_fma(a2, b2[jp], acc2[i][jp]);
            }
        }
        __syncthreads();
    }

#pragma unroll
    for (int i = 0; i < 5; i++) {
        int r = ty*5 + i;
        int p = r / KNN;
#pragma unroll
        for (int jp = 0; jp < 4; jp++) {
            float2 v = f2_unpack(acc2[i][jp]);
            pool[r*STG_STRIDE + tx*8 + 2*jp]     = v.x + sT[p*64 + tx*8 + 2*jp];
            pool[r*STG_STRIDE + tx*8 + 2*jp + 1] = v.y + sT[p*64 + tx*8 + 2*jp + 1];
        }
    }
    __syncthreads();

    int ol = tid & 63;
    int gi = tid >> 6;
    float s = 0.f, s2 = 0.f;
#pragma unroll
    for (int half = 0; half < 2; half++) {
        int p = gi + half*4;
        float mx = -INFINITY, mn = INFINITY;
#pragma unroll
        for (int k = 0; k < KNN; k++) {
            float v = pool[(p*KNN + k)*STG_STRIDE + ol];
            mx = fmaxf(mx, v); mn = fminf(mn, v);
            s += v; s2 += v*v;
        }
        size_t oi = (size_t)(p0 + p)*O + n0 + ol;
        hmax[oi] = mx;
        hmin[oi] = mn;
    }
    __syncthreads();
    sT[gi*64 + ol] = s;
    sT[256 + gi*64 + ol] = s2;
    __syncthreads();
    if (gi == 0) {
        float ts  = sT[ol] + sT[64+ol] + sT[128+ol] + sT[192+ol];
        float ts2 = sT[256+ol] + sT[320+ol] + sT[384+ol] + sT[448+ol];
        atomicAdd(&gsum[n0 + ol],  (double)ts);
        atomicAdd(&gsum2[n0 + ol], (double)ts2);
    }
}

// ---------------------------------------------------------------------------
// Column reduce for point convs (sum/sumsq per channel)
// ---------------------------------------------------------------------------
__global__ __launch_bounds__(256)
void colreduce_kernel(const float* __restrict__ P, int O,
                      double* __restrict__ gsum, double* __restrict__ gsum2) {
    int ol = threadIdx.x & 63;
    int gi = threadIdx.x >> 6;
    int o  = blockIdx.x*64 + ol;
    int r0 = blockIdx.y*256 + gi*64;
    float s = 0.f, s2 = 0.f;
    for (int r = r0; r < r0 + 64; r++) {
        float v = P[(size_t)r*O + o];
        s += v; s2 += v*v;
    }
    __shared__ float ss[4][64], ssq[4][64];
    ss[gi][ol] = s; ssq[gi][ol] = s2;
    __syncthreads();
    if (gi == 0) {
        atomicAdd(&gsum[o],  (double)(ss[0][ol]+ss[1][ol]+ss[2][ol]+ss[3][ol]));
        atomicAdd(&gsum2[o], (double)(ssq[0][ol]+ssq[1][ol]+ssq[2][ol]+ssq[3][ol]));
    }
}

__global__ void bn_params_kernel(const double* __restrict__ gsum, const double* __restrict__ gsum2,
                                 const float* __restrict__ g, const float* __restrict__ b,
                                 int O, double cnt,
                                 float* __restrict__ scale, float* __restrict__ shift) {
    int o = threadIdx.x;
    if (o >= O) return;
    double m   = gsum[o] / cnt;
    double var = gsum2[o] / cnt - m*m;
    float sc = g[o] * rsqrtf((float)var + BN_EPS);
    scale[o] = sc;
    shift[o] = b[o] - (float)m * sc;
}

__global__ void edge_finalize_kernel(const float* __restrict__ hmax, const float* __restrict__ hmin,
                                     const float* __restrict__ scale, const float* __restrict__ shift,
                                     float* __restrict__ out, int O) {
    int i = blockIdx.x*256 + threadIdx.x;
    if (i >= BNTOT*O) return;
    int o = i & (O - 1);
    float sc = scale[o];
    float v = (sc >= 0.f ? hmax[i] : hmin[i]) * sc + shift[o];
    out[i] = v >= 0.f ? v : NEG_SLOPE*v;
}

// h6: act + global max over n per (b,o)
__global__ __launch_bounds__(256)
void h6_finalize_kernel(const float* __restrict__ P,
                        const float* __restrict__ scale, const float* __restrict__ shift,
                        float* __restrict__ gmax) {
    int ol = threadIdx.x & 63;
    int gi = threadIdx.x >> 6;
    int o = blockIdx.x*64 + ol;
    int b = blockIdx.y;
    float sc = scale[o], sh = shift[o];
    float mx = -INFINITY;
    for (int n = gi*512; n < (gi+1)*512; n++) {
        float v = P[((size_t)(b*NPTS + n))*256 + o]*sc + sh;
        v = v >= 0.f ? v : NEG_SLOPE*v;
        mx = fmaxf(mx, v);
    }
    __shared__ float sm[4][64];
    sm[gi][ol] = mx;
    __syncthreads();
    if (gi == 0)
        gmax[b*256 + o] = fmaxf(fmaxf(sm[0][ol], sm[1][ol]), fmaxf(sm[2][ol], sm[3][ol]));
}

__global__ void cat_kernel(const float* __restrict__ x1, const float* __restrict__ x2,
                           const float* __restrict__ x3, const float* __restrict__ x4,
                           const float* __restrict__ gmax, float* __restrict__ cat) {
    size_t i = (size_t)blockIdx.x*256 + threadIdx.x;
    if (i >= (size_t)BNTOT*768) return;
    int bn = (int)(i / 768);
    int c  = (int)(i - (size_t)bn*768);
    float v;
    if      (c < 64)  v = x1[bn*64  + c];
    else if (c < 128) v = x2[bn*64  + c - 64];
    else if (c < 256) v = x3[bn*128 + c - 128];
    else if (c < 512) v = x4[bn*256 + c - 256];
    else              v = gmax[(bn >> 11)*256 + c - 512];
    cat[i] = v;
}

// final: act + transpose (B,N,256) -> (B,256,N)
__global__ void out_transpose_kernel(const float* __restrict__ P,
                                     const float* __restrict__ scale, const float* __restrict__ shift,
                                     float* __restrict__ out) {
    __shared__ float tile[32][33];
    int b  = blockIdx.z;
    int n0 = blockIdx.x*32, o0 = blockIdx.y*32;
    int tx = threadIdx.x, ty = threadIdx.y;
    int o = o0 + tx;
    float v = P[((size_t)(b*NPTS + n0 + ty))*256 + o]*scale[o] + shift[o];
    v = v >= 0.f ? v : NEG_SLOPE*v;
    tile[ty][tx] = v;
    __syncthreads();
    out[(size_t)b*256*NPTS + (size_t)(o0 + ty)*NPTS + n0 + tx] = tile[tx][ty];
}

// ---------------------------------------------------------------------------
// Host side
// ---------------------------------------------------------------------------
static void* sym(const void* s) { void* p = nullptr; cudaGetSymbolAddress(&p, s); return p; }

extern "C" void kernel_launch(void* const* d_in, const int* in_sizes, int n_in,
                              void* d_out, int out_size) {
    const float* x  = (const float*)d_in[0];
    const float* W[4] = { (const float*)d_in[1], (const float*)d_in[4],
                          (const float*)d_in[7], (const float*)d_in[10] };
    const float* G[4] = { (const float*)d_in[2], (const float*)d_in[5],
                          (const float*)d_in[8], (const float*)d_in[11] };
    const float* Bb[4] = { (const float*)d_in[3], (const float*)d_in[6],
                           (const float*)d_in[9], (const float*)d_in[12] };
    const float* W6 = (const float*)d_in[13];
    const float* g6 = (const float*)d_in[14];
    const float* b6 = (const float*)d_in[15];
    const float* W5 = (const float*)d_in[16];
    const float* g5 = (const float*)d_in[17];
    const float* b5 = (const float*)d_in[18];

    float*  f0   = (float*)sym(g_f0);
    float*  x1   = (float*)sym(g_x1);
    float*  x2   = (float*)sym(g_x2);
    float*  x3   = (float*)sym(g_x3);
    float*  x4   = (float*)sym(g_x4);
    float*  pd   = (float*)sym(g_pd);
    int*    idx  = (int*)  sym(g_idx);
    float*  wa   = (float*)sym(g_wa);
    float*  wd   = (float*)sym(g_wd);
    float*  Tb   = (float*)sym(g_T);
    float*  hmax = (float*)sym(g_hmax);
    float*  hmin = (float*)sym(g_hmin);
    float*  Pb   = (float*)sym(g_P);
    float*  cat  = (float*)sym(g_cat);
    float*  gmax = (float*)sym(g_gmax);
    double* s0   = (double*)sym(g_sum);
    double* s2   = (double*)sym(g_sum2);
    float*  sc   = (float*)sym(g_scale);
    float*  sh   = (float*)sym(g_shift);

    // input transpose (B,3,N) -> (B,N,3)
    transpose_in_kernel<<<(NB*3*NPTS + 255)/256, 256>>>(x, f0);

    const float* feats[4] = { f0, x1, x2, x3 };
    float*       outs [4] = { x1, x2, x3, x4 };
    const int    Cs[4] = { 3, 64, 64, 128 };
    const int    Os[4] = { 64, 64, 128, 256 };

    for (int L = 0; L < 4; L++) {
        int C = Cs[L], O = Os[L];
        const float* feat = feats[L];

        prep_w_kernel<<<(O*C + 255)/256, 256>>>(W[L], O, C, wa, wd);
        gemm_nt_kernel<<<dim3((BNTOT + 127)/128, O/64), 256>>>(feat, wd, Tb, BNTOT, O, C);

        // kNN: symmetric negative squared distance + warp-per-row top-20
        dim3 ggrid(NPAIRS, 1, NB);
        if (C == 3) dist_sym_kernel<4><<<ggrid, 256>>>(feat, pd, C);
        else        dist_sym_kernel<16><<<ggrid, 256>>>(feat, pd, C);
        topk_warp_kernel<<<BNTOT/8, 256>>>(pd, idx);

        zero_stats_kernel<<<1, 256>>>(s0, s2);
        fused_edge_kernel<<<dim3(BNTOT/FP, O/64), 256>>>(
            feat, wa, Tb, idx, C, O, hmax, hmin, s0, s2);
        bn_params_kernel<<<1, 256>>>(s0, s2, G[L], Bb[L], O, (double)MEDGE, sc, sh);
        edge_finalize_kernel<<<(BNTOT*O + 255)/256, 256>>>(hmax, hmin, sc, sh, outs[L], O);
    }

    // --- point conv h6 = lrelu(bn(x4 . W6^T)), then x5 = max over n ---
    gemm_nt_kernel<<<dim3(BNTOT/128, 256/64), 256>>>(x4, W6, Pb, BNTOT, 256, 256);
    zero_stats_kernel<<<1, 256>>>(s0, s2);
    colreduce_kernel<<<dim3(256/64, BNTOT/256), 256>>>(Pb, 256, s0, s2);
    bn_params_kernel<<<1, 256>>>(s0, s2, g6, b6, 256, (double)BNTOT, sc, sh);
    h6_finalize_kernel<<<dim3(256/64, NB), 256>>>(Pb, sc, sh, gmax);

    // --- concat [x1,x2,x3,x4,x5] -> 768 ---
    cat_kernel<<<(int)(((size_t)BNTOT*768 + 255)/256), 256>>>(x1, x2, x3, x4, gmax, cat);

    // --- final point conv + transpose output ---
    gemm_nt_kernel<<<dim3(BNTOT/128, 256/64), 256>>>(cat, W5, Pb, BNTOT, 256, 768);
    zero_stats_kernel<<<1, 256>>>(s0, s2);
    colreduce_kernel<<<dim3(256/64, BNTOT/256), 256>>>(Pb, 256, s0, s2);
    bn_params_kernel<<<1, 256>>>(s0, s2, g5, b5, 256, (double)BNTOT, sc, sh);
    out_transpose_kernel<<<dim3(NPTS/32, 256/32, NB), dim3(32, 32)>>>(Pb, sc, sh, (float*)d_out);
}